// round 1
// baseline (speedup 1.0000x reference)
#include <cuda_runtime.h>
#include <cstdint>

#define BB 65536
#define XX 362
#define TM 64

// ---------------- scratch (device globals; no allocation) ----------------
__device__ float g_att [BB * 6];
__device__ int   g_idx [BB * 6];
__device__ float g_pred[BB * 6];
__device__ int   g_order[BB];
__device__ int   g_cnt [3];
__device__ int   g_base[3];
__device__ int   g_cur [3];

// ---------------- 0: reset counters (graph replays need this) ------------
__global__ void k_init() {
    if (threadIdx.x < 3) g_cnt[threadIdx.x] = 0;
}

// ---------------- 1: copy + argmax + gather ------------------------------
// one warp per row
__global__ void k_prep(const float* __restrict__ x, float* __restrict__ out) {
    int row  = blockIdx.x * 8 + (threadIdx.x >> 5);
    int lane = threadIdx.x & 31;
    const float* xr = x   + (size_t)row * XX;
    float*     orow = out + (size_t)row * XX;

    float bv = -3.4e38f;
    int   bi = 0;
    for (int i = lane; i < XX; i += 32) {
        float v = xr[i];
        orow[i] = v;
        if (v > bv) { bv = v; bi = i; }   // within-lane: first occurrence wins
    }
    #pragma unroll
    for (int off = 16; off > 0; off >>= 1) {
        float ov = __shfl_down_sync(0xffffffffu, bv, off);
        int   oi = __shfl_down_sync(0xffffffffu, bi, off);
        if (ov > bv || (ov == bv && oi < bi)) { bv = ov; bi = oi; }
    }
    int ptr = __shfl_sync(0xffffffffu, bi, 0);

    if (lane < 6) {
        int idx;
        if      (lane == 0) idx = 0;
        else if (lane == 1) idx = ptr;                 // unclamped, as in source
        else {
            int d = (lane == 2) ? -19 : (lane == 3) ? 19 : (lane == 4) ? -1 : 1;
            idx = ptr + d;
            idx = idx < 1 ? 1 : (idx > XX - 1 ? XX - 1 : idx);
        }
        g_idx[row * 6 + lane] = idx;
        g_att[row * 6 + lane] = xr[idx];
    }
}

// ---------------- 2: histogram of actions (warp-aggregated) --------------
__global__ void k_hist(const int* __restrict__ ba) {
    int i = blockIdx.x * blockDim.x + threadIdx.x;
    int a = ba[i];
    unsigned full = 0xffffffffu;
    unsigned m0 = __ballot_sync(full, a == 0);
    unsigned m1 = __ballot_sync(full, a == 1);
    unsigned m2 = __ballot_sync(full, a == 2);
    unsigned mk = (a == 0) ? m0 : (a == 1) ? m1 : m2;
    int lane = threadIdx.x & 31;
    if (((int)__ffs(mk) - 1) == lane) atomicAdd(&g_cnt[a], __popc(mk));
}

// ---------------- 3: exclusive scan of 3 bins ----------------------------
__global__ void k_offs() {
    g_base[0] = 0;
    g_base[1] = g_cnt[0];
    g_base[2] = g_cnt[0] + g_cnt[1];
    g_cur[0] = g_base[0];
    g_cur[1] = g_base[1];
    g_cur[2] = g_base[2];
}

// ---------------- 4: scatter sample ids into action groups ---------------
__global__ void k_assign(const int* __restrict__ ba) {
    int i = blockIdx.x * blockDim.x + threadIdx.x;
    int a = ba[i];
    unsigned full = 0xffffffffu;
    unsigned m0 = __ballot_sync(full, a == 0);
    unsigned m1 = __ballot_sync(full, a == 1);
    unsigned m2 = __ballot_sync(full, a == 2);
    unsigned mk = (a == 0) ? m0 : (a == 1) ? m1 : m2;
    int lane   = threadIdx.x & 31;
    int leader = (int)__ffs(mk) - 1;
    int rank   = __popc(mk & ((1u << lane) - 1u));
    int pos    = 0;
    if (lane == leader) pos = atomicAdd(&g_cur[a], __popc(mk));
    pos = __shfl_sync(full, pos, leader);
    g_order[pos + rank] = i;
}

// ---------------- 5: grouped MLP, 64 samples per block -------------------
// smem: s_att[TM*6] | s_h1[TM*100] (reused for h3) | s_h2[TM*404] | s_sid[TM]
__global__ void __launch_bounds__(256) k_mlp(
    const float* __restrict__ W1, const float* __restrict__ b1,
    const float* __restrict__ W2, const float* __restrict__ b2,
    const float* __restrict__ W3, const float* __restrict__ b3,
    const float* __restrict__ W4, const float* __restrict__ b4)
{
    int a   = blockIdx.y;
    int cnt = g_cnt[a];
    int m0  = blockIdx.x * TM;
    if (m0 >= cnt) return;
    int M     = min(TM, cnt - m0);
    int gbase = g_base[a];

    extern __shared__ float sm[];
    float* s_att = sm;                       // TM*6
    float* s_h1  = sm + TM * 6;              // TM*100  (stride 100)
    float* s_h2  = s_h1 + TM * 100;          // TM*404  (stride 404: no-conflict)
    int*   s_sid = (int*)(s_h2 + TM * 404);  // TM

    int t = threadIdx.x;
    if (t < TM) s_sid[t] = (t < M) ? g_order[gbase + m0 + t] : -1;
    __syncthreads();
    for (int idx = t; idx < TM * 6; idx += 256) {
        int sid = s_sid[idx / 6];
        s_att[idx] = (sid >= 0) ? g_att[sid * 6 + (idx % 6)] : 0.0f;
    }
    __syncthreads();

    int tx = t & 15;       // n dimension (16 threads)
    int ty = t >> 4;       // m dimension (16 groups of 4 rows)

    // ---- layer 1: att[64,6] @ W1[6,100] -> h1 ----
    {
        const float* W1a = W1 + a * 600;
        const float* b1a = b1 + a * 100;
        float av[4][6];
        #pragma unroll
        for (int i = 0; i < 4; i++)
            #pragma unroll
            for (int k = 0; k < 6; k++)
                av[i][k] = s_att[(ty * 4 + i) * 6 + k];
        #pragma unroll
        for (int j = 0; j < 7; j++) {
            int n = tx + 16 * j;
            if (n < 100) {
                float bb = b1a[n];
                #pragma unroll
                for (int i = 0; i < 4; i++) {
                    float acc = bb;
                    #pragma unroll
                    for (int k = 0; k < 6; k++)
                        acc += av[i][k] * W1a[k * 100 + n];
                    s_h1[(ty * 4 + i) * 100 + n] = fmaxf(acc, 0.0f);
                }
            }
        }
    }
    __syncthreads();

    // ---- layer 2: h1[64,100] @ W2[100,400] -> h2 ----
    {
        const float* W2a = W2 + a * 40000;
        const float* b2a = b2 + a * 400;
        for (int jc = 0; jc < 5; jc++) {
            int nb = tx + 80 * jc;           // n = nb + 16*jl,  jl<5
            float acc[4][5];
            #pragma unroll
            for (int jl = 0; jl < 5; jl++) {
                float bb = b2a[nb + 16 * jl];
                #pragma unroll
                for (int i = 0; i < 4; i++) acc[i][jl] = bb;
            }
            #pragma unroll 4
            for (int k = 0; k < 100; k++) {
                float h[4];
                #pragma unroll
                for (int i = 0; i < 4; i++) h[i] = s_h1[(ty * 4 + i) * 100 + k];
                const float* wr = W2a + k * 400 + nb;
                #pragma unroll
                for (int jl = 0; jl < 5; jl++) {
                    float w = wr[16 * jl];
                    #pragma unroll
                    for (int i = 0; i < 4; i++) acc[i][jl] += h[i] * w;
                }
            }
            #pragma unroll
            for (int i = 0; i < 4; i++)
                #pragma unroll
                for (int jl = 0; jl < 5; jl++)
                    s_h2[(ty * 4 + i) * 404 + nb + 16 * jl] = fmaxf(acc[i][jl], 0.0f);
        }
    }
    __syncthreads();

    // ---- layer 3: h2[64,400] @ W3[400,100] -> h3 (into s_h1) ----
    {
        const float* W3a = W3 + a * 40000;
        const float* b3a = b3 + a * 100;
        float acc[4][7];
        #pragma unroll
        for (int j = 0; j < 7; j++) {
            int n = tx + 16 * j;
            float bb = (n < 100) ? b3a[n] : 0.0f;
            #pragma unroll
            for (int i = 0; i < 4; i++) acc[i][j] = bb;
        }
        #pragma unroll 2
        for (int k = 0; k < 400; k++) {
            float h[4];
            #pragma unroll
            for (int i = 0; i < 4; i++) h[i] = s_h2[(ty * 4 + i) * 404 + k];
            const float* wr = W3a + k * 100;
            #pragma unroll
            for (int j = 0; j < 7; j++) {
                int n = tx + 16 * j;
                if (n < 100) {
                    float w = wr[n];
                    #pragma unroll
                    for (int i = 0; i < 4; i++) acc[i][j] += h[i] * w;
                }
            }
        }
        #pragma unroll
        for (int j = 0; j < 7; j++) {
            int n = tx + 16 * j;
            if (n < 100) {
                #pragma unroll
                for (int i = 0; i < 4; i++)
                    s_h1[(ty * 4 + i) * 100 + n] = fmaxf(acc[i][j], 0.0f);
            }
        }
    }
    __syncthreads();

    // ---- layer 4: h3[64,100] @ W4[100,6] -> pred (no relu) ----
    {
        const float* W4a = W4 + a * 600;
        const float* b4a = b4 + a * 6;
        for (int idx = t; idx < TM * 6; idx += 256) {
            int m = idx / 6, o = idx % 6;
            int sid = s_sid[m];
            if (sid >= 0) {
                float acc = b4a[o];
                #pragma unroll 4
                for (int k = 0; k < 100; k++)
                    acc += s_h1[m * 100 + k] * W4a[k * 6 + o];
                g_pred[sid * 6 + o] = acc;
            }
        }
    }
}

// ---------------- 6: scatter deltas (last j wins, program order) ---------
__global__ void k_scatter(float* __restrict__ out) {
    int i = blockIdx.x * blockDim.x + threadIdx.x;
    size_t rb = (size_t)i * XX;
    int b6 = i * 6;
    #pragma unroll
    for (int j = 0; j < 6; j++)
        out[rb + g_idx[b6 + j]] = g_att[b6 + j] + g_pred[b6 + j];
}

// ---------------- launch ----------------
extern "C" void kernel_launch(void* const* d_in, const int* in_sizes, int n_in,
                              void* d_out, int out_size) {
    const float* x  = (const float*)d_in[0];
    const float* W1 = (const float*)d_in[1];
    const float* b1 = (const float*)d_in[2];
    const float* W2 = (const float*)d_in[3];
    const float* b2 = (const float*)d_in[4];
    const float* W3 = (const float*)d_in[5];
    const float* b3 = (const float*)d_in[6];
    const float* W4 = (const float*)d_in[7];
    const float* b4 = (const float*)d_in[8];
    const int*   ba = (const int*)d_in[9];
    float* out = (float*)d_out;

    int smem = (TM * 6 + TM * 100 + TM * 404 + TM) * 4;   // 130816 bytes
    cudaFuncSetAttribute(k_mlp, cudaFuncAttributeMaxDynamicSharedMemorySize, smem);

    k_init<<<1, 32>>>();
    k_prep<<<BB / 8, 256>>>(x, out);
    k_hist<<<BB / 256, 256>>>(ba);
    k_offs<<<1, 1>>>();
    k_assign<<<BB / 256, 256>>>(ba);
    dim3 g((BB + TM - 1) / TM, 3);
    k_mlp<<<g, 256, smem>>>(W1, b1, W2, b2, W3, b3, W4, b4);
    k_scatter<<<BB / 256, 256>>>(out);
}

// round 2
// speedup vs baseline: 2.2246x; 2.2246x over previous
#include <cuda_runtime.h>
#include <cstdint>

#define BB 65536
#define XX 362
#define TM 64

// ---------------- scratch (device globals; no allocation) ----------------
__device__ float g_att [BB * 6];
__device__ int   g_idx [BB * 6];
__device__ float g_pred[BB * 6];
__device__ int   g_order[BB];
__device__ int   g_cnt [3];
__device__ int   g_base[3];
__device__ int   g_cur [3];

// ---------------- 0: reset counters (graph replays need this) ------------
__global__ void k_init() {
    if (threadIdx.x < 3) g_cnt[threadIdx.x] = 0;
}

// ---------------- 1: copy + argmax + gather ------------------------------
__global__ void k_prep(const float* __restrict__ x, float* __restrict__ out) {
    int row  = blockIdx.x * 8 + (threadIdx.x >> 5);
    int lane = threadIdx.x & 31;
    const float* xr = x   + (size_t)row * XX;
    float*     orow = out + (size_t)row * XX;

    float bv = -3.4e38f;
    int   bi = 0;
    for (int i = lane; i < XX; i += 32) {
        float v = xr[i];
        orow[i] = v;
        if (v > bv) { bv = v; bi = i; }
    }
    #pragma unroll
    for (int off = 16; off > 0; off >>= 1) {
        float ov = __shfl_down_sync(0xffffffffu, bv, off);
        int   oi = __shfl_down_sync(0xffffffffu, bi, off);
        if (ov > bv || (ov == bv && oi < bi)) { bv = ov; bi = oi; }
    }
    int ptr = __shfl_sync(0xffffffffu, bi, 0);

    if (lane < 6) {
        int idx;
        if      (lane == 0) idx = 0;
        else if (lane == 1) idx = ptr;                 // unclamped, as in source
        else {
            int d = (lane == 2) ? -19 : (lane == 3) ? 19 : (lane == 4) ? -1 : 1;
            idx = ptr + d;
            idx = idx < 1 ? 1 : (idx > XX - 1 ? XX - 1 : idx);
        }
        g_idx[row * 6 + lane] = idx;
        g_att[row * 6 + lane] = xr[idx];
    }
}

// ---------------- 2: histogram of actions (warp-aggregated) --------------
__global__ void k_hist(const int* __restrict__ ba) {
    int i = blockIdx.x * blockDim.x + threadIdx.x;
    int a = ba[i];
    unsigned full = 0xffffffffu;
    unsigned m0 = __ballot_sync(full, a == 0);
    unsigned m1 = __ballot_sync(full, a == 1);
    unsigned m2 = __ballot_sync(full, a == 2);
    unsigned mk = (a == 0) ? m0 : (a == 1) ? m1 : m2;
    int lane = threadIdx.x & 31;
    if (((int)__ffs(mk) - 1) == lane) atomicAdd(&g_cnt[a], __popc(mk));
}

// ---------------- 3: exclusive scan of 3 bins ----------------------------
__global__ void k_offs() {
    g_base[0] = 0;
    g_base[1] = g_cnt[0];
    g_base[2] = g_cnt[0] + g_cnt[1];
    g_cur[0] = g_base[0];
    g_cur[1] = g_base[1];
    g_cur[2] = g_base[2];
}

// ---------------- 4: scatter sample ids into action groups ---------------
__global__ void k_assign(const int* __restrict__ ba) {
    int i = blockIdx.x * blockDim.x + threadIdx.x;
    int a = ba[i];
    unsigned full = 0xffffffffu;
    unsigned m0 = __ballot_sync(full, a == 0);
    unsigned m1 = __ballot_sync(full, a == 1);
    unsigned m2 = __ballot_sync(full, a == 2);
    unsigned mk = (a == 0) ? m0 : (a == 1) ? m1 : m2;
    int lane   = threadIdx.x & 31;
    int leader = (int)__ffs(mk) - 1;
    int rank   = __popc(mk & ((1u << lane) - 1u));
    int pos    = 0;
    if (lane == leader) pos = atomicAdd(&g_cur[a], __popc(mk));
    pos = __shfl_sync(full, pos, leader);
    g_order[pos + rank] = i;
}

// ---------------- 5: grouped MLP, 64 samples per block, layers 2+3 fused --
// smem: s_att[TM*6] | s_h1[TM*100] (h1, later h3) | s_h2c[TM*101] (h2 chunk)
//       | s_sid[TM]   -> 53248 bytes total, 3 blocks/SM
__global__ void __launch_bounds__(256, 3) k_mlp(
    const float* __restrict__ W1, const float* __restrict__ b1,
    const float* __restrict__ W2, const float* __restrict__ b2,
    const float* __restrict__ W3, const float* __restrict__ b3,
    const float* __restrict__ W4, const float* __restrict__ b4)
{
    int a   = blockIdx.y;
    int cnt = g_cnt[a];
    int m0  = blockIdx.x * TM;
    if (m0 >= cnt) return;
    int M     = min(TM, cnt - m0);
    int gbase = g_base[a];

    extern __shared__ float sm[];
    float* s_att = sm;                        // TM*6
    float* s_h1  = sm + TM * 6;               // TM*100 (stride 100)
    float* s_h2c = s_h1 + TM * 100;           // TM*101 (stride 101: conflict-free)
    int*   s_sid = (int*)(s_h2c + TM * 101);  // TM

    int t = threadIdx.x;
    if (t < TM) s_sid[t] = (t < M) ? g_order[gbase + m0 + t] : -1;
    __syncthreads();
    for (int idx = t; idx < TM * 6; idx += 256) {
        int sid = s_sid[idx / 6];
        s_att[idx] = (sid >= 0) ? g_att[sid * 6 + (idx % 6)] : 0.0f;
    }
    __syncthreads();

    int tx = t & 15;       // n dimension (16 threads)
    int ty = t >> 4;       // m dimension (16 groups of 4 rows)

    // ---- layer 1: att[64,6] @ W1[6,100] -> h1 ----
    {
        const float* W1a = W1 + a * 600;
        const float* b1a = b1 + a * 100;
        float av[4][6];
        #pragma unroll
        for (int i = 0; i < 4; i++)
            #pragma unroll
            for (int k = 0; k < 6; k++)
                av[i][k] = s_att[(ty * 4 + i) * 6 + k];
        #pragma unroll
        for (int j = 0; j < 7; j++) {
            int n = tx + 16 * j;
            if (n < 100) {
                float bb = b1a[n];
                #pragma unroll
                for (int i = 0; i < 4; i++) {
                    float acc = bb;
                    #pragma unroll
                    for (int k = 0; k < 6; k++)
                        acc += av[i][k] * W1a[k * 100 + n];
                    s_h1[(ty * 4 + i) * 100 + n] = fmaxf(acc, 0.0f);
                }
            }
        }
    }
    __syncthreads();

    // ---- fused layers 2+3: h2 chunked (4 x 100 cols), layer-3 acc in regs ----
    const float* W2a = W2 + a * 40000;
    const float* b2a = b2 + a * 400;
    const float* W3a = W3 + a * 40000;
    const float* b3a = b3 + a * 100;

    float acc3[4][7];
    #pragma unroll
    for (int j = 0; j < 7; j++) {
        int n = tx + 16 * j;
        float bb = (n < 100) ? b3a[n] : 0.0f;
        #pragma unroll
        for (int i = 0; i < 4; i++) acc3[i][j] = bb;
    }

    for (int c = 0; c < 4; c++) {
        // layer-2 partial: h2 cols [100c, 100c+100)
        const float* W2c = W2a + 100 * c;
        float acc2[4][7];
        #pragma unroll
        for (int j = 0; j < 7; j++) {
            int n = tx + 16 * j;
            float bb = (n < 100) ? b2a[100 * c + n] : 0.0f;
            #pragma unroll
            for (int i = 0; i < 4; i++) acc2[i][j] = bb;
        }
        #pragma unroll 4
        for (int k = 0; k < 100; k++) {
            float h[4];
            #pragma unroll
            for (int i = 0; i < 4; i++) h[i] = s_h1[(ty * 4 + i) * 100 + k];
            const float* wr = W2c + k * 400;
            #pragma unroll
            for (int j = 0; j < 7; j++) {
                int n = tx + 16 * j;
                if (n < 100) {
                    float w = wr[n];
                    #pragma unroll
                    for (int i = 0; i < 4; i++) acc2[i][j] += h[i] * w;
                }
            }
        }
        #pragma unroll
        for (int j = 0; j < 7; j++) {
            int n = tx + 16 * j;
            if (n < 100) {
                #pragma unroll
                for (int i = 0; i < 4; i++)
                    s_h2c[(ty * 4 + i) * 101 + n] = fmaxf(acc2[i][j], 0.0f);
            }
        }
        __syncthreads();

        // layer-3 partial over kk in [100c, 100c+100)
        const float* W3c = W3a + 100 * c * 100;
        #pragma unroll 4
        for (int k = 0; k < 100; k++) {
            float h[4];
            #pragma unroll
            for (int i = 0; i < 4; i++) h[i] = s_h2c[(ty * 4 + i) * 101 + k];
            const float* wr = W3c + k * 100;
            #pragma unroll
            for (int j = 0; j < 7; j++) {
                int n = tx + 16 * j;
                if (n < 100) {
                    float w = wr[n];
                    #pragma unroll
                    for (int i = 0; i < 4; i++) acc3[i][j] += h[i] * w;
                }
            }
        }
        __syncthreads();
    }

    // ---- relu(h3) -> s_h1 ----
    #pragma unroll
    for (int j = 0; j < 7; j++) {
        int n = tx + 16 * j;
        if (n < 100) {
            #pragma unroll
            for (int i = 0; i < 4; i++)
                s_h1[(ty * 4 + i) * 100 + n] = fmaxf(acc3[i][j], 0.0f);
        }
    }
    __syncthreads();

    // ---- layer 4: h3[64,100] @ W4[100,6] -> pred (no relu) ----
    {
        const float* W4a = W4 + a * 600;
        const float* b4a = b4 + a * 6;
        for (int idx = t; idx < TM * 6; idx += 256) {
            int m = idx / 6, o = idx % 6;
            int sid = s_sid[m];
            if (sid >= 0) {
                float acc = b4a[o];
                #pragma unroll 4
                for (int k = 0; k < 100; k++)
                    acc += s_h1[m * 100 + k] * W4a[k * 6 + o];
                g_pred[sid * 6 + o] = acc;
            }
        }
    }
}

// ---------------- 6: scatter deltas (last j wins, program order) ---------
__global__ void k_scatter(float* __restrict__ out) {
    int i = blockIdx.x * blockDim.x + threadIdx.x;
    size_t rb = (size_t)i * XX;
    int b6 = i * 6;
    #pragma unroll
    for (int j = 0; j < 6; j++)
        out[rb + g_idx[b6 + j]] = g_att[b6 + j] + g_pred[b6 + j];
}

// ---------------- launch ----------------
extern "C" void kernel_launch(void* const* d_in, const int* in_sizes, int n_in,
                              void* d_out, int out_size) {
    const float* x  = (const float*)d_in[0];
    const float* W1 = (const float*)d_in[1];
    const float* b1 = (const float*)d_in[2];
    const float* W2 = (const float*)d_in[3];
    const float* b2 = (const float*)d_in[4];
    const float* W3 = (const float*)d_in[5];
    const float* b3 = (const float*)d_in[6];
    const float* W4 = (const float*)d_in[7];
    const float* b4 = (const float*)d_in[8];
    const int*   ba = (const int*)d_in[9];
    float* out = (float*)d_out;

    int smem = (TM * 6 + TM * 100 + TM * 101 + TM) * 4;   // 53248 bytes
    cudaFuncSetAttribute(k_mlp, cudaFuncAttributeMaxDynamicSharedMemorySize, smem);

    k_init<<<1, 32>>>();
    k_prep<<<BB / 8, 256>>>(x, out);
    k_hist<<<BB / 256, 256>>>(ba);
    k_offs<<<1, 1>>>();
    k_assign<<<BB / 256, 256>>>(ba);
    dim3 g((BB + TM - 1) / TM, 3);
    k_mlp<<<g, 256, smem>>>(W1, b1, W2, b2, W3, b3, W4, b4);
    k_scatter<<<BB / 256, 256>>>(out);
}

// round 3
// speedup vs baseline: 5.6759x; 2.5515x over previous
#include <cuda_runtime.h>
#include <cuda_bf16.h>
#include <cstdint>

#define BB 65536
#define XX 362
#define TM 64

#define H1S 120   // h1 smem row stride (bf16 elems), K=100 padded to 112, stride 120
#define H2S 88    // h2 chunk smem row stride, K-chunk 80, stride 88
#define W2S 88    // W2 stage row stride (112 rows x 88 cols)
#define W3S 120   // W3 stage row stride (80 rows x 120 cols)

// smem byte offsets
#define OFF_H1H 0
#define OFF_H1L 15360
#define OFF_H2H 30720
#define OFF_H2L 41984
#define OFF_W   53248
#define OFF_WL  72960
#define OFF_ATT 92672
#define OFF_SID 94720
#define SMEM_TOT 94976

// ---------------- scratch (device globals; no allocation) ----------------
__device__ float g_att [BB * 6];
__device__ int   g_idx [BB * 6];
__device__ float g_pred[BB * 6];
__device__ int   g_order[BB];
__device__ int   g_cnt [3];
__device__ int   g_base[3];
__device__ int   g_cur [3];
// split-bf16 weights: W2 [a][100][400]; W3 padded [a][400][112]
__device__ __align__(16) __nv_bfloat16 g_w2h[3 * 40000];
__device__ __align__(16) __nv_bfloat16 g_w2l[3 * 40000];
__device__ __align__(16) __nv_bfloat16 g_w3h[3 * 400 * 112];
__device__ __align__(16) __nv_bfloat16 g_w3l[3 * 400 * 112];

// ---------------- mma helpers ----------------
__device__ __forceinline__ uint32_t smaddr(const void* p) {
    return (uint32_t)__cvta_generic_to_shared(p);
}
__device__ __forceinline__ void ldsm4(uint32_t a, uint32_t& r0, uint32_t& r1,
                                      uint32_t& r2, uint32_t& r3) {
    asm volatile("ldmatrix.sync.aligned.m8n8.x4.shared.b16 {%0,%1,%2,%3},[%4];"
                 : "=r"(r0), "=r"(r1), "=r"(r2), "=r"(r3) : "r"(a));
}
__device__ __forceinline__ void ldsm4t(uint32_t a, uint32_t& r0, uint32_t& r1,
                                       uint32_t& r2, uint32_t& r3) {
    asm volatile("ldmatrix.sync.aligned.m8n8.x4.trans.shared.b16 {%0,%1,%2,%3},[%4];"
                 : "=r"(r0), "=r"(r1), "=r"(r2), "=r"(r3) : "r"(a));
}
__device__ __forceinline__ void mma16816(float (&d)[4], uint32_t a0, uint32_t a1,
                                         uint32_t a2, uint32_t a3,
                                         uint32_t b0, uint32_t b1) {
    asm volatile(
        "mma.sync.aligned.m16n8k16.row.col.f32.bf16.bf16.f32 "
        "{%0,%1,%2,%3},{%4,%5,%6,%7},{%8,%9},{%0,%1,%2,%3};"
        : "+f"(d[0]), "+f"(d[1]), "+f"(d[2]), "+f"(d[3])
        : "r"(a0), "r"(a1), "r"(a2), "r"(a3), "r"(b0), "r"(b1));
}
__device__ __forceinline__ void bsplit(float v, __nv_bfloat16& h, __nv_bfloat16& l) {
    h = __float2bfloat16(v);
    l = __float2bfloat16(v - __bfloat162float(h));
}

// ---------------- 0: reset counters ----------------
__global__ void k_init() {
    if (threadIdx.x < 3) g_cnt[threadIdx.x] = 0;
}

// ---------------- 0b: split weights to bf16 hi/lo ----------------
__global__ void k_convw(const float* __restrict__ W2, const float* __restrict__ W3) {
    int i = blockIdx.x * 256 + threadIdx.x;
    if (i < 3 * 40000) {
        float v = W2[i];
        __nv_bfloat16 h, l; bsplit(v, h, l);
        g_w2h[i] = h; g_w2l[i] = l;
    }
    if (i < 3 * 400 * 112) {
        int an = i / 44800, r = (i % 44800) / 112, c = i % 112;
        float v = (c < 100) ? W3[an * 40000 + r * 100 + c] : 0.0f;
        __nv_bfloat16 h, l; bsplit(v, h, l);
        g_w3h[i] = h; g_w3l[i] = l;
    }
}

// ---------------- 1: copy + argmax + gather ----------------
__global__ void k_prep(const float* __restrict__ x, float* __restrict__ out) {
    int row  = blockIdx.x * 8 + (threadIdx.x >> 5);
    int lane = threadIdx.x & 31;
    const float* xr = x   + (size_t)row * XX;
    float*     orow = out + (size_t)row * XX;

    float bv = -3.4e38f;
    int   bi = 0;
    for (int i = lane; i < XX; i += 32) {
        float v = xr[i];
        orow[i] = v;
        if (v > bv) { bv = v; bi = i; }
    }
    #pragma unroll
    for (int off = 16; off > 0; off >>= 1) {
        float ov = __shfl_down_sync(0xffffffffu, bv, off);
        int   oi = __shfl_down_sync(0xffffffffu, bi, off);
        if (ov > bv || (ov == bv && oi < bi)) { bv = ov; bi = oi; }
    }
    int ptr = __shfl_sync(0xffffffffu, bi, 0);

    if (lane < 6) {
        int idx;
        if      (lane == 0) idx = 0;
        else if (lane == 1) idx = ptr;                 // unclamped, as in source
        else {
            int d = (lane == 2) ? -19 : (lane == 3) ? 19 : (lane == 4) ? -1 : 1;
            idx = ptr + d;
            idx = idx < 1 ? 1 : (idx > XX - 1 ? XX - 1 : idx);
        }
        g_idx[row * 6 + lane] = idx;
        g_att[row * 6 + lane] = xr[idx];
    }
}

// ---------------- 2: histogram ----------------
__global__ void k_hist(const int* __restrict__ ba) {
    int i = blockIdx.x * blockDim.x + threadIdx.x;
    int a = ba[i];
    unsigned full = 0xffffffffu;
    unsigned m0 = __ballot_sync(full, a == 0);
    unsigned m1 = __ballot_sync(full, a == 1);
    unsigned m2 = __ballot_sync(full, a == 2);
    unsigned mk = (a == 0) ? m0 : (a == 1) ? m1 : m2;
    int lane = threadIdx.x & 31;
    if (((int)__ffs(mk) - 1) == lane) atomicAdd(&g_cnt[a], __popc(mk));
}

// ---------------- 3: scan ----------------
__global__ void k_offs() {
    g_base[0] = 0;
    g_base[1] = g_cnt[0];
    g_base[2] = g_cnt[0] + g_cnt[1];
    g_cur[0] = g_base[0]; g_cur[1] = g_base[1]; g_cur[2] = g_base[2];
}

// ---------------- 4: assign ----------------
__global__ void k_assign(const int* __restrict__ ba) {
    int i = blockIdx.x * blockDim.x + threadIdx.x;
    int a = ba[i];
    unsigned full = 0xffffffffu;
    unsigned m0 = __ballot_sync(full, a == 0);
    unsigned m1 = __ballot_sync(full, a == 1);
    unsigned m2 = __ballot_sync(full, a == 2);
    unsigned mk = (a == 0) ? m0 : (a == 1) ? m1 : m2;
    int lane   = threadIdx.x & 31;
    int leader = (int)__ffs(mk) - 1;
    int rank   = __popc(mk & ((1u << lane) - 1u));
    int pos    = 0;
    if (lane == leader) pos = atomicAdd(&g_cur[a], __popc(mk));
    pos = __shfl_sync(full, pos, leader);
    g_order[pos + rank] = i;
}

// ---------------- 5: grouped MLP with split-bf16 tensor cores ----------------
__global__ void __launch_bounds__(256, 2) k_mlp(
    const float* __restrict__ W1, const float* __restrict__ b1,
    const float* __restrict__ b2, const float* __restrict__ b3,
    const float* __restrict__ W4, const float* __restrict__ b4)
{
    int a   = blockIdx.y;
    int cnt = g_cnt[a];
    int m0b = blockIdx.x * TM;
    if (m0b >= cnt) return;
    int M     = min(TM, cnt - m0b);
    int gbase = g_base[a];

    extern __shared__ char smraw[];
    __nv_bfloat16* s_h1h = (__nv_bfloat16*)(smraw + OFF_H1H);
    __nv_bfloat16* s_h1l = (__nv_bfloat16*)(smraw + OFF_H1L);
    __nv_bfloat16* s_h2h = (__nv_bfloat16*)(smraw + OFF_H2H);
    __nv_bfloat16* s_h2l = (__nv_bfloat16*)(smraw + OFF_H2L);
    __nv_bfloat16* s_wh  = (__nv_bfloat16*)(smraw + OFF_W);
    __nv_bfloat16* s_wl  = (__nv_bfloat16*)(smraw + OFF_WL);
    float*         s_att = (float*)(smraw + OFF_ATT);
    int*           s_sid = (int*)(smraw + OFF_SID);

    int t    = threadIdx.x;
    int lane = t & 31;
    int warp = t >> 5;
    int wm   = warp & 3;          // m-tile (16 rows)
    int wn   = warp >> 2;         // n-half
    int tg   = lane & 3;
    int gg   = lane >> 2;
    int lsel = lane & 15;
    int csel = (lane >> 4) * 8;

    if (t < TM) s_sid[t] = (t < M) ? g_order[gbase + m0b + t] : -1;

    // stage W1 + b1 into wstage region (as fp32)
    float* s_w1 = (float*)(smraw + OFF_W);       // 700 floats
    {
        const float4* W1a4 = (const float4*)(W1 + a * 600);
        const float4* b1a4 = (const float4*)(b1 + a * 100);
        for (int i = t; i < 175; i += 256)
            ((float4*)s_w1)[i] = (i < 150) ? W1a4[i] : b1a4[i - 150];
    }
    __syncthreads();
    for (int i = t; i < TM * 6; i += 256) {
        int sid = s_sid[i / 6];
        s_att[(i / 6) * 8 + (i % 6)] = (sid >= 0) ? g_att[sid * 6 + (i % 6)] : 0.0f;
    }
    __syncthreads();

    // ---- L1 (fp32 cores): h1 = relu(att@W1+b1), split to bf16 hi/lo, zero pad ----
    for (int i = t; i < TM * H1S; i += 256) {
        int m = i / H1S, n = i - m * H1S;
        float v = 0.0f;
        if (n < 100) {
            v = s_w1[600 + n];
            #pragma unroll
            for (int k = 0; k < 6; k++) v += s_att[m * 8 + k] * s_w1[k * 100 + n];
            v = fmaxf(v, 0.0f);
        }
        __nv_bfloat16 h, l; bsplit(v, h, l);
        s_h1h[i] = h; s_h1l[i] = l;
    }

    const __nv_bfloat16* W2hp = g_w2h + a * 40000;
    const __nv_bfloat16* W2lp = g_w2l + a * 40000;
    const __nv_bfloat16* W3hp = g_w3h + a * 44800;
    const __nv_bfloat16* W3lp = g_w3l + a * 44800;
    const float* b2a = b2 + a * 400;
    const float* b3a = b3 + a * 100;

    uint32_t h1h_b = smaddr(s_h1h), h1l_b = smaddr(s_h1l);
    uint32_t h2h_b = smaddr(s_h2h), h2l_b = smaddr(s_h2l);
    uint32_t wh_b  = smaddr(s_wh),  wl_b  = smaddr(s_wl);

    // L3 accumulators (held across chunks)
    float acc3[7][4];
    #pragma unroll
    for (int nt = 0; nt < 7; nt++) {
        int n = wn * 56 + nt * 8 + 2 * tg;
        float b0 = (n     < 100) ? b3a[n]     : 0.0f;
        float b1v= (n + 1 < 100) ? b3a[n + 1] : 0.0f;
        acc3[nt][0] = b0; acc3[nt][1] = b1v; acc3[nt][2] = b0; acc3[nt][3] = b1v;
    }

    for (int c = 0; c < 5; c++) {
        __syncthreads();
        // ---- stage W2 chunk: [112 k][88 n] (real k<100, n<80) ----
        for (int i = t; i < 112 * 11; i += 256) {
            int k = i / 11, q = i - k * 11;
            uint4 vh = make_uint4(0, 0, 0, 0), vl = make_uint4(0, 0, 0, 0);
            if (k < 100 && q < 10) {
                vh = *(const uint4*)&W2hp[k * 400 + 80 * c + 8 * q];
                vl = *(const uint4*)&W2lp[k * 400 + 80 * c + 8 * q];
            }
            *(uint4*)&s_wh[k * W2S + 8 * q] = vh;
            *(uint4*)&s_wl[k * W2S + 8 * q] = vl;
        }
        __syncthreads();

        // ---- L2 MMA: h1[64,112] @ W2c[112,80] -> acc2 ----
        float acc2[5][4];
        #pragma unroll
        for (int nt = 0; nt < 5; nt++) {
            int n = 80 * c + wn * 40 + nt * 8 + 2 * tg;
            float b0 = b2a[n], b1v = b2a[n + 1];
            acc2[nt][0] = b0; acc2[nt][1] = b1v; acc2[nt][2] = b0; acc2[nt][3] = b1v;
        }
        #pragma unroll
        for (int ks = 0; ks < 7; ks++) {
            uint32_t aoff = (uint32_t)(((wm * 16 + lsel) * H1S + 16 * ks + csel) * 2);
            uint32_t ah0, ah1, ah2, ah3, al0, al1, al2, al3;
            ldsm4(h1h_b + aoff, ah0, ah1, ah2, ah3);
            ldsm4(h1l_b + aoff, al0, al1, al2, al3);
            #pragma unroll
            for (int p = 0; p < 3; p++) {
                uint32_t boff = (uint32_t)(((16 * ks + lsel) * W2S + wn * 40 + 16 * p + csel) * 2);
                uint32_t bh0, bh1, bh2, bh3, bl0, bl1, bl2, bl3;
                ldsm4t(wh_b + boff, bh0, bh1, bh2, bh3);
                ldsm4t(wl_b + boff, bl0, bl1, bl2, bl3);
                mma16816(acc2[2 * p], ah0, ah1, ah2, ah3, bh0, bh1);
                mma16816(acc2[2 * p], ah0, ah1, ah2, ah3, bl0, bl1);
                mma16816(acc2[2 * p], al0, al1, al2, al3, bh0, bh1);
                if (p < 2) {
                    mma16816(acc2[2 * p + 1], ah0, ah1, ah2, ah3, bh2, bh3);
                    mma16816(acc2[2 * p + 1], ah0, ah1, ah2, ah3, bl2, bl3);
                    mma16816(acc2[2 * p + 1], al0, al1, al2, al3, bh2, bh3);
                }
            }
        }
        // ---- epilogue: relu + split -> s_h2 (chunk-local cols 0..79) ----
        #pragma unroll
        for (int nt = 0; nt < 5; nt++) {
            int n = wn * 40 + nt * 8 + 2 * tg;
            #pragma unroll
            for (int hh = 0; hh < 2; hh++) {
                int row = wm * 16 + gg + 8 * hh;
                float v0 = fmaxf(acc2[nt][2 * hh + 0], 0.0f);
                float v1 = fmaxf(acc2[nt][2 * hh + 1], 0.0f);
                __nv_bfloat16 h0, l0, h1v, l1v;
                bsplit(v0, h0, l0); bsplit(v1, h1v, l1v);
                s_h2h[row * H2S + n]     = h0;
                s_h2h[row * H2S + n + 1] = h1v;
                s_h2l[row * H2S + n]     = l0;
                s_h2l[row * H2S + n + 1] = l1v;
            }
        }
        __syncthreads();

        // ---- stage W3 chunk: [80 k][120 n] (real n<112 from padded global) ----
        for (int i = t; i < 80 * 15; i += 256) {
            int k = i / 15, q = i - k * 15;
            uint4 vh = make_uint4(0, 0, 0, 0), vl = make_uint4(0, 0, 0, 0);
            if (q < 14) {
                vh = *(const uint4*)&W3hp[(80 * c + k) * 112 + 8 * q];
                vl = *(const uint4*)&W3lp[(80 * c + k) * 112 + 8 * q];
            }
            *(uint4*)&s_wh[k * W3S + 8 * q] = vh;
            *(uint4*)&s_wl[k * W3S + 8 * q] = vl;
        }
        __syncthreads();

        // ---- L3 MMA: h2c[64,80] @ W3c[80,112] -> acc3 (accumulate) ----
        #pragma unroll
        for (int ks = 0; ks < 5; ks++) {
            uint32_t aoff = (uint32_t)(((wm * 16 + lsel) * H2S + 16 * ks + csel) * 2);
            uint32_t ah0, ah1, ah2, ah3, al0, al1, al2, al3;
            ldsm4(h2h_b + aoff, ah0, ah1, ah2, ah3);
            ldsm4(h2l_b + aoff, al0, al1, al2, al3);
            #pragma unroll
            for (int p = 0; p < 4; p++) {
                uint32_t boff = (uint32_t)(((16 * ks + lsel) * W3S + wn * 56 + 16 * p + csel) * 2);
                uint32_t bh0, bh1, bh2, bh3, bl0, bl1, bl2, bl3;
                ldsm4t(wh_b + boff, bh0, bh1, bh2, bh3);
                ldsm4t(wl_b + boff, bl0, bl1, bl2, bl3);
                mma16816(acc3[2 * p], ah0, ah1, ah2, ah3, bh0, bh1);
                mma16816(acc3[2 * p], ah0, ah1, ah2, ah3, bl0, bl1);
                mma16816(acc3[2 * p], al0, al1, al2, al3, bh0, bh1);
                if (p < 3) {
                    mma16816(acc3[2 * p + 1], ah0, ah1, ah2, ah3, bh2, bh3);
                    mma16816(acc3[2 * p + 1], ah0, ah1, ah2, ah3, bl2, bl3);
                    mma16816(acc3[2 * p + 1], al0, al1, al2, al3, bh2, bh3);
                }
            }
        }
    }
    __syncthreads();

    // ---- h3 epilogue (fp32) into wstage region + stage W4/b4 ----
    float* s_h3 = (float*)(smraw + OFF_W);                 // [64][104]
    float* s_w4 = (float*)(smraw + OFF_W + TM * 104 * 4);  // 600 + 8
    #pragma unroll
    for (int nt = 0; nt < 7; nt++) {
        int n = wn * 56 + nt * 8 + 2 * tg;
        #pragma unroll
        for (int hh = 0; hh < 2; hh++) {
            int row = wm * 16 + gg + 8 * hh;
            if (n     < 100) s_h3[row * 104 + n]     = fmaxf(acc3[nt][2 * hh + 0], 0.0f);
            if (n + 1 < 100) s_h3[row * 104 + n + 1] = fmaxf(acc3[nt][2 * hh + 1], 0.0f);
        }
    }
    {
        const float4* W4a4 = (const float4*)(W4 + a * 600);
        for (int i = t; i < 150; i += 256) ((float4*)s_w4)[i] = W4a4[i];
        if (t < 6) s_w4[600 + t] = b4[a * 6 + t];
    }
    __syncthreads();

    // ---- L4 (fp32 cores): pred = h3 @ W4 + b4 ----
    for (int i = t; i < TM * 6; i += 256) {
        int m = i / 6, o = i - m * 6;
        int sid = s_sid[m];
        if (sid >= 0) {
            float acc = s_w4[600 + o];
            #pragma unroll 4
            for (int k = 0; k < 100; k++)
                acc += s_h3[m * 104 + k] * s_w4[k * 6 + o];
            g_pred[sid * 6 + o] = acc;
        }
    }
}

// ---------------- 6: scatter deltas (last j wins) ----------------
__global__ void k_scatter(float* __restrict__ out) {
    int i = blockIdx.x * blockDim.x + threadIdx.x;
    size_t rb = (size_t)i * XX;
    int b6 = i * 6;
    #pragma unroll
    for (int j = 0; j < 6; j++)
        out[rb + g_idx[b6 + j]] = g_att[b6 + j] + g_pred[b6 + j];
}

// ---------------- launch ----------------
extern "C" void kernel_launch(void* const* d_in, const int* in_sizes, int n_in,
                              void* d_out, int out_size) {
    const float* x  = (const float*)d_in[0];
    const float* W1 = (const float*)d_in[1];
    const float* b1 = (const float*)d_in[2];
    const float* W2 = (const float*)d_in[3];
    const float* b2 = (const float*)d_in[4];
    const float* W3 = (const float*)d_in[5];
    const float* b3 = (const float*)d_in[6];
    const float* W4 = (const float*)d_in[7];
    const float* b4 = (const float*)d_in[8];
    const int*   ba = (const int*)d_in[9];
    float* out = (float*)d_out;

    cudaFuncSetAttribute(k_mlp, cudaFuncAttributeMaxDynamicSharedMemorySize, SMEM_TOT);

    k_init<<<1, 32>>>();
    k_convw<<<(3 * 400 * 112 + 255) / 256, 256>>>(W2, W3);
    k_prep<<<BB / 8, 256>>>(x, out);
    k_hist<<<BB / 256, 256>>>(ba);
    k_offs<<<1, 1>>>();
    k_assign<<<BB / 256, 256>>>(ba);
    dim3 g((BB + TM - 1) / TM, 3);
    k_mlp<<<g, 256, SMEM_TOT>>>(W1, b1, b2, b3, W4, b4);
    k_scatter<<<BB / 256, 256>>>(out);
}

// round 6
// speedup vs baseline: 6.1188x; 1.0780x over previous
#include <cuda_runtime.h>
#include <cuda_bf16.h>
#include <cstdint>

#define BB 65536
#define XX 362
#define TM 128

#define H1S 120   // h1 smem row stride (bf16), K padded 100->112
#define H2S 88    // h2 chunk row stride, k-chunk 80
#define W2S 88    // W2 stage stride (112 rows x 88 cols region, 100 real rows)
#define W3S 120   // W3 stage stride (80 rows x 120 cols region, 112 real cols)
#define H3S 101   // h3 fp32 row stride

// smem byte offsets (all 16B aligned)
#define OFF_H1H 0
#define OFF_H1L 30720
#define OFF_H2H 61440
#define OFF_H2L 83968
#define OFF_WAH 106496
#define OFF_WAL 126208
#define OFF_WBH 145920
#define OFF_WBL 165632
#define OFF_ATT 185344
#define OFF_SID 189440
#define SMEM_TOT 189952

// ---------------- scratch (device globals; no allocation) ----------------
__device__ float g_att [BB * 6];
__device__ int   g_idx [BB * 6];
__device__ int   g_order[3 * BB];      // per-action regions
__device__ int   g_cnt [3];
// split-bf16 weights: W2 [a][100][400]; W3 padded [a][400][112]
__device__ __align__(16) __nv_bfloat16 g_w2h[3 * 40000];
__device__ __align__(16) __nv_bfloat16 g_w2l[3 * 40000];
__device__ __align__(16) __nv_bfloat16 g_w3h[3 * 400 * 112];
__device__ __align__(16) __nv_bfloat16 g_w3l[3 * 400 * 112];

// ---------------- helpers ----------------
__device__ __forceinline__ uint32_t smaddr(const void* p) {
    return (uint32_t)__cvta_generic_to_shared(p);
}
__device__ __forceinline__ void ldsm4(uint32_t a, uint32_t& r0, uint32_t& r1,
                                      uint32_t& r2, uint32_t& r3) {
    asm volatile("ldmatrix.sync.aligned.m8n8.x4.shared.b16 {%0,%1,%2,%3},[%4];"
                 : "=r"(r0), "=r"(r1), "=r"(r2), "=r"(r3) : "r"(a));
}
__device__ __forceinline__ void ldsm4t(uint32_t a, uint32_t& r0, uint32_t& r1,
                                       uint32_t& r2, uint32_t& r3) {
    asm volatile("ldmatrix.sync.aligned.m8n8.x4.trans.shared.b16 {%0,%1,%2,%3},[%4];"
                 : "=r"(r0), "=r"(r1), "=r"(r2), "=r"(r3) : "r"(a));
}
__device__ __forceinline__ void mma16816(float (&d)[4], uint32_t a0, uint32_t a1,
                                         uint32_t a2, uint32_t a3,
                                         uint32_t b0, uint32_t b1) {
    asm volatile(
        "mma.sync.aligned.m16n8k16.row.col.f32.bf16.bf16.f32 "
        "{%0,%1,%2,%3},{%4,%5,%6,%7},{%8,%9},{%0,%1,%2,%3};"
        : "+f"(d[0]), "+f"(d[1]), "+f"(d[2]), "+f"(d[3])
        : "r"(a0), "r"(a1), "r"(a2), "r"(a3), "r"(b0), "r"(b1));
}
__device__ __forceinline__ void bsplit(float v, __nv_bfloat16& h, __nv_bfloat16& l) {
    h = __float2bfloat16(v);
    l = __float2bfloat16(v - __bfloat162float(h));
}
__device__ __forceinline__ void cp16(uint32_t dst, const void* src) {
    asm volatile("cp.async.cg.shared.global [%0], [%1], 16;" :: "r"(dst), "l"(src));
}
#define CP_COMMIT() asm volatile("cp.async.commit_group;")
#define CP_WAIT1()  asm volatile("cp.async.wait_group 1;")
#define CP_WAIT0()  asm volatile("cp.async.wait_group 0;")

// ---------------- 0: split weights to bf16 hi/lo (+ reset counters) ------
__global__ void k_convw(const float* __restrict__ W2, const float* __restrict__ W3) {
    int i = blockIdx.x * 256 + threadIdx.x;
    if (blockIdx.x == 0 && threadIdx.x < 3) g_cnt[threadIdx.x] = 0;
    if (i < 3 * 40000) {
        float v = W2[i];
        __nv_bfloat16 h, l; bsplit(v, h, l);
        g_w2h[i] = h; g_w2l[i] = l;
    }
    if (i < 3 * 400 * 112) {
        int an = i / 44800, r = (i % 44800) / 112, c = i % 112;
        float v = (c < 100) ? W3[an * 40000 + r * 100 + c] : 0.0f;
        __nv_bfloat16 h, l; bsplit(v, h, l);
        g_w3h[i] = h; g_w3l[i] = l;
    }
}

// ---------------- 1: copy + argmax + gather ----------------
__global__ void k_prep(const float* __restrict__ x, float* __restrict__ out) {
    int row  = blockIdx.x * 8 + (threadIdx.x >> 5);
    int lane = threadIdx.x & 31;
    const float* xr = x   + (size_t)row * XX;
    float*     orow = out + (size_t)row * XX;

    float bv = -3.4e38f;
    int   bi = 0;
    for (int i = lane; i < XX; i += 32) {
        float v = xr[i];
        orow[i] = v;
        if (v > bv) { bv = v; bi = i; }
    }
    #pragma unroll
    for (int off = 16; off > 0; off >>= 1) {
        float ov = __shfl_down_sync(0xffffffffu, bv, off);
        int   oi = __shfl_down_sync(0xffffffffu, bi, off);
        if (ov > bv || (ov == bv && oi < bi)) { bv = ov; bi = oi; }
    }
    int ptr = __shfl_sync(0xffffffffu, bi, 0);

    if (lane < 6) {
        int idx;
        if      (lane == 0) idx = 0;
        else if (lane == 1) idx = ptr;                 // unclamped, as in source
        else {
            int d = (lane == 2) ? -19 : (lane == 3) ? 19 : (lane == 4) ? -1 : 1;
            idx = ptr + d;
            idx = idx < 1 ? 1 : (idx > XX - 1 ? XX - 1 : idx);
        }
        g_idx[row * 6 + lane] = idx;
        g_att[row * 6 + lane] = xr[idx];
    }
}

// ---------------- 2: single-pass grouping by action ----------------
__global__ void k_assign(const int* __restrict__ ba) {
    int i = blockIdx.x * blockDim.x + threadIdx.x;
    int a = ba[i];
    unsigned full = 0xffffffffu;
    unsigned m0 = __ballot_sync(full, a == 0);
    unsigned m1 = __ballot_sync(full, a == 1);
    unsigned m2 = __ballot_sync(full, a == 2);
    unsigned mk = (a == 0) ? m0 : (a == 1) ? m1 : m2;
    int lane   = threadIdx.x & 31;
    int leader = (int)__ffs(mk) - 1;
    int rank   = __popc(mk & ((1u << lane) - 1u));
    int pos    = 0;
    if (lane == leader) pos = atomicAdd(&g_cnt[a], __popc(mk));
    pos = __shfl_sync(full, pos, leader);
    g_order[a * BB + pos + rank] = i;
}

// ---------------- 3: grouped MLP, TM=128, cp.async pipelined --------------
__global__ void __launch_bounds__(512, 1) k_mlp(
    const float* __restrict__ W1, const float* __restrict__ b1,
    const float* __restrict__ b2, const float* __restrict__ b3,
    const float* __restrict__ W4, const float* __restrict__ b4,
    float* __restrict__ out)
{
    int a   = blockIdx.y;
    int cnt = g_cnt[a];
    int m0b = blockIdx.x * TM;
    if (m0b >= cnt) return;
    int M = min(TM, cnt - m0b);

    extern __shared__ char smraw[];
    __nv_bfloat16* s_h1h = (__nv_bfloat16*)(smraw + OFF_H1H);
    __nv_bfloat16* s_h1l = (__nv_bfloat16*)(smraw + OFF_H1L);
    __nv_bfloat16* s_h2h = (__nv_bfloat16*)(smraw + OFF_H2H);
    __nv_bfloat16* s_h2l = (__nv_bfloat16*)(smraw + OFF_H2L);
    float*         s_att = (float*)(smraw + OFF_ATT);
    int*           s_sid = (int*)(smraw + OFF_SID);

    const __nv_bfloat16* W2hp = g_w2h + a * 40000;
    const __nv_bfloat16* W2lp = g_w2l + a * 40000;
    const __nv_bfloat16* W3hp = g_w3h + a * 44800;
    const __nv_bfloat16* W3lp = g_w3l + a * 44800;

    uint32_t sbase = smaddr(smraw);
    uint32_t h1h_b = sbase + OFF_H1H, h1l_b = sbase + OFF_H1L;
    uint32_t h2h_b = sbase + OFF_H2H, h2l_b = sbase + OFF_H2L;
    uint32_t wah_b = sbase + OFF_WAH, wal_b = sbase + OFF_WAL;
    uint32_t wbh_b = sbase + OFF_WBH, wbl_b = sbase + OFF_WBL;

    int t    = threadIdx.x;
    int lane = t & 31;
    int warp = t >> 5;
    int wm   = warp & 7;          // m-tile (16 rows each, 8 tiles)
    int wn   = warp >> 3;         // n-half
    int tg   = lane & 3;
    int gg   = lane >> 2;
    int lsel = lane & 15;
    int csel = (lane >> 4) * 8;

    // ---- prologue: sid, prefetch chunk-0 weights, zero W2 pad rows ----
    if (t < TM) s_sid[t] = (t < M) ? g_order[a * BB + m0b + t] : -1;

    // stage W2 chunk 0 -> bufA
    for (int i = t; i < 1000; i += 512) {
        int k = i / 10, q = i - k * 10;
        uint32_t doff = (uint32_t)((k * W2S + 8 * q) * 2);
        size_t soff = (size_t)k * 400 + 8 * q;      // c=0
        cp16(wah_b + doff, W2hp + soff);
        cp16(wal_b + doff, W2lp + soff);
    }
    CP_COMMIT();
    // stage W3 chunk 0 -> bufB
    for (int i = t; i < 1120; i += 512) {
        int k = i / 14, q = i - k * 14;
        uint32_t doff = (uint32_t)((k * W3S + 8 * q) * 2);
        size_t soff = (size_t)k * 112 + 8 * q;      // c=0
        cp16(wbh_b + doff, W3hp + soff);
        cp16(wbl_b + doff, W3lp + soff);
    }
    CP_COMMIT();
    // zero W2 pad rows 100..111 (k-padding; once — cp.async never touches them)
    for (int i = t; i < 528; i += 512) {
        ((uint32_t*)(smraw + OFF_WAH))[4400 + i] = 0;
        ((uint32_t*)(smraw + OFF_WAL))[4400 + i] = 0;
    }
    __syncthreads();

    for (int i = t; i < TM * 6; i += 512) {
        int m = i / 6, j = i - m * 6;
        int sid = s_sid[m];
        s_att[m * 8 + j] = (sid >= 0) ? g_att[sid * 6 + j] : 0.0f;
    }
    __syncthreads();

    // ---- L1 (fp32): h1 = relu(att@W1+b1) -> split bf16, pad cols zero ----
    {
        const float* W1a = W1 + a * 600;
        const float* b1a = b1 + a * 100;
        for (int i = t; i < TM * H1S; i += 512) {
            int m = i / H1S, n = i - m * H1S;
            float v = 0.0f;
            if (n < 100) {
                v = __ldg(b1a + n);
                #pragma unroll
                for (int k = 0; k < 6; k++) v += s_att[m * 8 + k] * __ldg(W1a + k * 100 + n);
                v = fmaxf(v, 0.0f);
            }
            __nv_bfloat16 h, l; bsplit(v, h, l);
            s_h1h[i] = h; s_h1l[i] = l;
        }
    }

    const float* b2a = b2 + a * 400;
    const float* b3a = b3 + a * 100;

    // L3 accumulators persist across chunks
    float acc3[7][4];
    #pragma unroll
    for (int nt = 0; nt < 7; nt++) {
        int n = wn * 56 + nt * 8 + 2 * tg;
        float v0 = (n     < 100) ? __ldg(b3a + n)     : 0.0f;
        float v1 = (n + 1 < 100) ? __ldg(b3a + n + 1) : 0.0f;
        acc3[nt][0] = v0; acc3[nt][1] = v1; acc3[nt][2] = v0; acc3[nt][3] = v1;
    }

    for (int c = 0; c < 5; c++) {
        CP_WAIT1();
        __syncthreads();                       // W2(c) ready in bufA; h1/h2 coherent

        // ---- L2 MMA: h1[128,112] @ W2c[112,80] ----
        float acc2[5][4];
        #pragma unroll
        for (int nt = 0; nt < 5; nt++) {
            int n = 80 * c + wn * 40 + nt * 8 + 2 * tg;
            float v0 = __ldg(b2a + n), v1 = __ldg(b2a + n + 1);
            acc2[nt][0] = v0; acc2[nt][1] = v1; acc2[nt][2] = v0; acc2[nt][3] = v1;
        }
        #pragma unroll
        for (int ks = 0; ks < 7; ks++) {
            uint32_t aoff = (uint32_t)(((wm * 16 + lsel) * H1S + 16 * ks + csel) * 2);
            uint32_t ah0, ah1, ah2, ah3, al0, al1, al2, al3;
            ldsm4(h1h_b + aoff, ah0, ah1, ah2, ah3);
            ldsm4(h1l_b + aoff, al0, al1, al2, al3);
            #pragma unroll
            for (int p = 0; p < 3; p++) {
                uint32_t boff = (uint32_t)(((16 * ks + lsel) * W2S + wn * 40 + 16 * p + csel) * 2);
                uint32_t bh0, bh1, bh2, bh3, bl0, bl1, bl2, bl3;
                ldsm4t(wah_b + boff, bh0, bh1, bh2, bh3);
                ldsm4t(wal_b + boff, bl0, bl1, bl2, bl3);
                mma16816(acc2[2 * p], ah0, ah1, ah2, ah3, bh0, bh1);
                mma16816(acc2[2 * p], ah0, ah1, ah2, ah3, bl0, bl1);
                mma16816(acc2[2 * p], al0, al1, al2, al3, bh0, bh1);
                if (p < 2) {
                    mma16816(acc2[2 * p + 1], ah0, ah1, ah2, ah3, bh2, bh3);
                    mma16816(acc2[2 * p + 1], ah0, ah1, ah2, ah3, bl2, bl3);
                    mma16816(acc2[2 * p + 1], al0, al1, al2, al3, bh2, bh3);
                }
            }
        }
        // ---- epilogue: relu + split -> h2 (chunk-local cols) ----
        #pragma unroll
        for (int nt = 0; nt < 5; nt++) {
            int n = wn * 40 + nt * 8 + 2 * tg;
            #pragma unroll
            for (int hh = 0; hh < 2; hh++) {
                int row = wm * 16 + gg + 8 * hh;
                float v0 = fmaxf(acc2[nt][2 * hh + 0], 0.0f);
                float v1 = fmaxf(acc2[nt][2 * hh + 1], 0.0f);
                __nv_bfloat16 h0, l0, h1v, l1v;
                bsplit(v0, h0, l0); bsplit(v1, h1v, l1v);
                s_h2h[row * H2S + n]     = h0;
                s_h2h[row * H2S + n + 1] = h1v;
                s_h2l[row * H2S + n]     = l0;
                s_h2l[row * H2S + n + 1] = l1v;
            }
        }
        __syncthreads();                        // h2 visible; bufA free

        if (c < 4) {                            // prefetch W2(c+1) -> bufA
            for (int i = t; i < 1000; i += 512) {
                int k = i / 10, q = i - k * 10;
                uint32_t doff = (uint32_t)((k * W2S + 8 * q) * 2);
                size_t soff = (size_t)k * 400 + 80 * (c + 1) + 8 * q;
                cp16(wah_b + doff, W2hp + soff);
                cp16(wal_b + doff, W2lp + soff);
            }
            CP_COMMIT();
            CP_WAIT1();                         // W3(c) done (W2(c+1) may pend)
        } else {
            CP_WAIT0();                         // last W3 must be done
        }
        __syncthreads();                        // bufB coherent across threads

        // ---- L3 MMA: h2c[128,80] @ W3c[80,112] (accumulate) ----
        #pragma unroll
        for (int ks = 0; ks < 5; ks++) {
            uint32_t aoff = (uint32_t)(((wm * 16 + lsel) * H2S + 16 * ks + csel) * 2);
            uint32_t ah0, ah1, ah2, ah3, al0, al1, al2, al3;
            ldsm4(h2h_b + aoff, ah0, ah1, ah2, ah3);
            ldsm4(h2l_b + aoff, al0, al1, al2, al3);
            #pragma unroll
            for (int p = 0; p < 4; p++) {
                uint32_t boff = (uint32_t)(((16 * ks + lsel) * W3S + wn * 56 + 16 * p + csel) * 2);
                uint32_t bh0, bh1, bh2, bh3, bl0, bl1, bl2, bl3;
                ldsm4t(wbh_b + boff, bh0, bh1, bh2, bh3);
                ldsm4t(wbl_b + boff, bl0, bl1, bl2, bl3);
                mma16816(acc3[2 * p], ah0, ah1, ah2, ah3, bh0, bh1);
                mma16816(acc3[2 * p], ah0, ah1, ah2, ah3, bl0, bl1);
                mma16816(acc3[2 * p], al0, al1, al2, al3, bh0, bh1);
                if (p < 3) {
                    mma16816(acc3[2 * p + 1], ah0, ah1, ah2, ah3, bh2, bh3);
                    mma16816(acc3[2 * p + 1], ah0, ah1, ah2, ah3, bl2, bl3);
                    mma16816(acc3[2 * p + 1], al0, al1, al2, al3, bh2, bh3);
                }
            }
        }
        __syncthreads();                        // bufB free; h2 free

        if (c < 4) {                            // prefetch W3(c+1) -> bufB
            for (int i = t; i < 1120; i += 512) {
                int k = i / 14, q = i - k * 14;
                uint32_t doff = (uint32_t)((k * W3S + 8 * q) * 2);
                size_t soff = (size_t)(80 * (c + 1) + k) * 112 + 8 * q;
                cp16(wbh_b + doff, W3hp + soff);
                cp16(wbl_b + doff, W3lp + soff);
            }
            CP_COMMIT();
        }
    }

    // ---- h3 = relu(acc3) -> fp32 smem (reuses h1 region; safe post-barrier) ----
    float* s_h3 = (float*)(smraw + OFF_H1H);    // [128][101]
    #pragma unroll
    for (int nt = 0; nt < 7; nt++) {
        int n = wn * 56 + nt * 8 + 2 * tg;
        #pragma unroll
        for (int hh = 0; hh < 2; hh++) {
            int row = wm * 16 + gg + 8 * hh;
            if (n     < 100) s_h3[row * H3S + n]     = fmaxf(acc3[nt][2 * hh + 0], 0.0f);
            if (n + 1 < 100) s_h3[row * H3S + n + 1] = fmaxf(acc3[nt][2 * hh + 1], 0.0f);
        }
    }
    __syncthreads();

    // ---- L4 + scatter fused: one thread per row, 6 stores in program order ----
    if (t < TM) {
        int sid = s_sid[t];
        if (sid >= 0) {
            const float* W4a = W4 + a * 600;
            float acc[6];
            #pragma unroll
            for (int o = 0; o < 6; o++) acc[o] = __ldg(b4 + a * 6 + o);
            #pragma unroll 4
            for (int k = 0; k < 100; k++) {
                float h = s_h3[t * H3S + k];
                #pragma unroll
                for (int o = 0; o < 6; o++) acc[o] += h * __ldg(W4a + k * 6 + o);
            }
            size_t rb = (size_t)sid * XX;
            int b6 = sid * 6;
            #pragma unroll
            for (int j = 0; j < 6; j++)
                out[rb + g_idx[b6 + j]] = g_att[b6 + j] + acc[j];
        }
    }
}

// ---------------- launch ----------------
extern "C" void kernel_launch(void* const* d_in, const int* in_sizes, int n_in,
                              void* d_out, int out_size) {
    const float* x  = (const float*)d_in[0];
    const float* W1 = (const float*)d_in[1];
    const float* b1 = (const float*)d_in[2];
    const float* W2 = (const float*)d_in[3];
    const float* b2 = (const float*)d_in[4];
    const float* W3 = (const float*)d_in[5];
    const float* b3 = (const float*)d_in[6];
    const float* W4 = (const float*)d_in[7];
    const float* b4 = (const float*)d_in[8];
    const int*   ba = (const int*)d_in[9];
    float* out = (float*)d_out;

    cudaFuncSetAttribute(k_mlp, cudaFuncAttributeMaxDynamicSharedMemorySize, SMEM_TOT);

    k_convw<<<(3 * 400 * 112 + 255) / 256, 256>>>(W2, W3);
    k_prep<<<BB / 8, 256>>>(x, out);
    k_assign<<<BB / 256, 256>>>(ba);
    dim3 g((BB + TM - 1) / TM, 3);
    k_mlp<<<g, 512, SMEM_TOT>>>(W1, b1, b2, b3, W4, b4, out);
}

// round 7
// speedup vs baseline: 6.4093x; 1.0475x over previous
#include <cuda_runtime.h>
#include <cuda_bf16.h>
#include <cstdint>

#define BB 65536
#define XX 362
#define TM 128

#define H1S 120   // h1 bf16 row stride (100 real, pad zeros to 112+)
#define H2S 88    // h2 bf16 row stride (80 real)
#define W2S 88    // W2 stage stride: 112 k-rows x 88 (80 real n)
#define W3S 120   // W3 stage stride: 80 k-rows x 120 (112 real n)
#define H3S 101

// smem byte offsets (all 128B aligned)
#define OFF_H1   0         // 30720
#define OFF_H2   30720     // 2 x 22528
#define H2B      22528
#define OFF_W2H  75776     // 19712
#define OFF_W2L  95488     // 19712
#define OFF_W3H  115200    // 19200
#define OFF_W3L  134400    // 19200
#define OFF_ATT  153600    // 4096
#define OFF_SID  157696    // 512
#define SMEM_TOT 158208

// ---------------- scratch ----------------
__device__ float g_att [BB * 6];
__device__ int   g_idx [BB * 6];
__device__ int   g_order[3 * BB];
__device__ int   g_cnt [3];
__device__ __align__(16) __nv_bfloat16 g_w2h[3 * 40000];
__device__ __align__(16) __nv_bfloat16 g_w2l[3 * 40000];
__device__ __align__(16) __nv_bfloat16 g_w3h[3 * 400 * 112];
__device__ __align__(16) __nv_bfloat16 g_w3l[3 * 400 * 112];

// ---------------- helpers ----------------
__device__ __forceinline__ uint32_t smaddr(const void* p) {
    return (uint32_t)__cvta_generic_to_shared(p);
}
__device__ __forceinline__ void ldsm4(uint32_t a, uint32_t& r0, uint32_t& r1,
                                      uint32_t& r2, uint32_t& r3) {
    asm volatile("ldmatrix.sync.aligned.m8n8.x4.shared.b16 {%0,%1,%2,%3},[%4];"
                 : "=r"(r0), "=r"(r1), "=r"(r2), "=r"(r3) : "r"(a));
}
__device__ __forceinline__ void ldsm4t(uint32_t a, uint32_t& r0, uint32_t& r1,
                                       uint32_t& r2, uint32_t& r3) {
    asm volatile("ldmatrix.sync.aligned.m8n8.x4.trans.shared.b16 {%0,%1,%2,%3},[%4];"
                 : "=r"(r0), "=r"(r1), "=r"(r2), "=r"(r3) : "r"(a));
}
__device__ __forceinline__ void mma16816(float (&d)[4], uint32_t a0, uint32_t a1,
                                         uint32_t a2, uint32_t a3,
                                         uint32_t b0, uint32_t b1) {
    asm volatile(
        "mma.sync.aligned.m16n8k16.row.col.f32.bf16.bf16.f32 "
        "{%0,%1,%2,%3},{%4,%5,%6,%7},{%8,%9},{%0,%1,%2,%3};"
        : "+f"(d[0]), "+f"(d[1]), "+f"(d[2]), "+f"(d[3])
        : "r"(a0), "r"(a1), "r"(a2), "r"(a3), "r"(b0), "r"(b1));
}
__device__ __forceinline__ void bsplit(float v, __nv_bfloat16& h, __nv_bfloat16& l) {
    h = __float2bfloat16(v);
    l = __float2bfloat16(v - __bfloat162float(h));
}
__device__ __forceinline__ void cp16(uint32_t dst, const void* src) {
    asm volatile("cp.async.cg.shared.global [%0], [%1], 16;" :: "r"(dst), "l"(src));
}
#define CP_COMMIT() asm volatile("cp.async.commit_group;")
#define CP_WAIT0()  asm volatile("cp.async.wait_group 0;")
#define BAR1() asm volatile("bar.sync 1, 512;" ::: "memory")
#define BAR2() asm volatile("bar.sync 2, 512;" ::: "memory")

// ---------------- 0: split weights hi/lo + reset counters ----------------
__global__ void k_convw(const float* __restrict__ W2, const float* __restrict__ W3) {
    int i = blockIdx.x * 256 + threadIdx.x;
    if (blockIdx.x == 0 && threadIdx.x < 3) g_cnt[threadIdx.x] = 0;
    if (i < 3 * 40000) {
        float v = W2[i];
        __nv_bfloat16 h, l; bsplit(v, h, l);
        g_w2h[i] = h; g_w2l[i] = l;
    }
    if (i < 3 * 400 * 112) {
        int an = i / 44800, r = (i % 44800) / 112, c = i % 112;
        float v = (c < 100) ? W3[an * 40000 + r * 100 + c] : 0.0f;
        __nv_bfloat16 h, l; bsplit(v, h, l);
        g_w3h[i] = h; g_w3l[i] = l;
    }
}

// ---------------- 1: copy + argmax + gather ----------------
__global__ void k_prep(const float* __restrict__ x, float* __restrict__ out) {
    int row  = blockIdx.x * 8 + (threadIdx.x >> 5);
    int lane = threadIdx.x & 31;
    const float* xr = x   + (size_t)row * XX;
    float*     orow = out + (size_t)row * XX;

    float bv = -3.4e38f;
    int   bi = 0;
    for (int i = lane; i < XX; i += 32) {
        float v = xr[i];
        orow[i] = v;
        if (v > bv) { bv = v; bi = i; }
    }
    #pragma unroll
    for (int off = 16; off > 0; off >>= 1) {
        float ov = __shfl_down_sync(0xffffffffu, bv, off);
        int   oi = __shfl_down_sync(0xffffffffu, bi, off);
        if (ov > bv || (ov == bv && oi < bi)) { bv = ov; bi = oi; }
    }
    int ptr = __shfl_sync(0xffffffffu, bi, 0);

    if (lane < 6) {
        int idx;
        if      (lane == 0) idx = 0;
        else if (lane == 1) idx = ptr;                 // unclamped, as in source
        else {
            int d = (lane == 2) ? -19 : (lane == 3) ? 19 : (lane == 4) ? -1 : 1;
            idx = ptr + d;
            idx = idx < 1 ? 1 : (idx > XX - 1 ? XX - 1 : idx);
        }
        g_idx[row * 6 + lane] = idx;
        g_att[row * 6 + lane] = xr[idx];
    }
}

// ---------------- 2: group samples by action ----------------
__global__ void k_assign(const int* __restrict__ ba) {
    int i = blockIdx.x * blockDim.x + threadIdx.x;
    int a = ba[i];
    unsigned full = 0xffffffffu;
    unsigned m0 = __ballot_sync(full, a == 0);
    unsigned m1 = __ballot_sync(full, a == 1);
    unsigned m2 = __ballot_sync(full, a == 2);
    unsigned mk = (a == 0) ? m0 : (a == 1) ? m1 : m2;
    int lane   = threadIdx.x & 31;
    int leader = (int)__ffs(mk) - 1;
    int rank   = __popc(mk & ((1u << lane) - 1u));
    int pos    = 0;
    if (lane == leader) pos = atomicAdd(&g_cnt[a], __popc(mk));
    pos = __shfl_sync(full, pos, leader);
    g_order[a * BB + pos + rank] = i;
}

// ---------------- 3: warp-specialized MLP (L2-warps | L3-warps) ----------
__global__ void __launch_bounds__(1024, 1) k_mlp(
    const float* __restrict__ W1, const float* __restrict__ b1,
    const float* __restrict__ b2, const float* __restrict__ b3,
    const float* __restrict__ W4, const float* __restrict__ b4,
    float* __restrict__ out)
{
    int a   = blockIdx.y;
    int cnt = g_cnt[a];
    int m0b = blockIdx.x * TM;
    if (m0b >= cnt) return;
    int M = min(TM, cnt - m0b);

    extern __shared__ char smraw[];
    __nv_bfloat16* s_h1  = (__nv_bfloat16*)(smraw + OFF_H1);
    float*         s_att = (float*)(smraw + OFF_ATT);
    int*           s_sid = (int*)(smraw + OFF_SID);

    const __nv_bfloat16* W2hp = g_w2h + a * 40000;
    const __nv_bfloat16* W2lp = g_w2l + a * 40000;
    const __nv_bfloat16* W3hp = g_w3h + a * 44800;
    const __nv_bfloat16* W3lp = g_w3l + a * 44800;

    uint32_t sbase = smaddr(smraw);
    uint32_t h1_b  = sbase + OFF_H1;
    uint32_t w2h_b = sbase + OFF_W2H, w2l_b = sbase + OFF_W2L;
    uint32_t w3h_b = sbase + OFF_W3H, w3l_b = sbase + OFF_W3L;

    int t    = threadIdx.x;
    int lane = t & 31;
    int warp = t >> 5;
    bool isL2 = warp < 16;
    int gt   = isL2 ? t : (t - 512);
    int gw   = warp & 15;
    int wm   = gw & 7;            // 8 m-tiles of 16 rows
    int wn   = gw >> 3;           // 2 n-halves
    int tg   = lane & 3;
    int gg   = lane >> 2;
    int lsel = lane & 15;
    int csel = (lane >> 4) * 8;

    // ---- prologue ----
    if (t < TM) s_sid[t] = (t < M) ? g_order[a * BB + m0b + t] : -1;

    if (isL2) {
        // stage W2(0); zero W2 k-pad rows 100..111 (written once, never cp'd)
        for (int i = gt; i < 1000; i += 512) {
            int k = i / 10, q = i - k * 10;
            uint32_t doff = (uint32_t)((k * W2S + 8 * q) * 2);
            size_t soff = (size_t)k * 400 + 8 * q;
            cp16(w2h_b + doff, W2hp + soff);
            cp16(w2l_b + doff, W2lp + soff);
        }
        CP_COMMIT();
        for (int i = gt; i < 528; i += 512) {
            ((uint32_t*)(smraw + OFF_W2H))[4400 + i] = 0;
            ((uint32_t*)(smraw + OFF_W2L))[4400 + i] = 0;
        }
    } else {
        // stage W3(0)
        for (int i = gt; i < 1120; i += 512) {
            int k = i / 14, q = i - k * 14;
            uint32_t doff = (uint32_t)((k * W3S + 8 * q) * 2);
            size_t soff = (size_t)k * 112 + 8 * q;
            cp16(w3h_b + doff, W3hp + soff);
            cp16(w3l_b + doff, W3lp + soff);
        }
        CP_COMMIT();
    }
    __syncthreads();

    for (int i = t; i < TM * 6; i += 1024) {
        int m = i / 6, j = i - m * 6;
        int sid = s_sid[m];
        s_att[m * 8 + j] = (sid >= 0) ? g_att[sid * 6 + j] : 0.0f;
    }
    __syncthreads();

    // ---- L1 (fp32): h1 = relu(att@W1+b1) -> single bf16, pad zeros ----
    {
        const float* W1a = W1 + a * 600;
        const float* b1a = b1 + a * 100;
        for (int i = t; i < TM * H1S; i += 1024) {
            int m = i / H1S, n = i - m * H1S;
            float v = 0.0f;
            if (n < 100) {
                v = __ldg(b1a + n);
                #pragma unroll
                for (int k = 0; k < 6; k++) v += s_att[m * 8 + k] * __ldg(W1a + k * 100 + n);
                v = fmaxf(v, 0.0f);
            }
            s_h1[i] = __float2bfloat16(v);
        }
    }

    const float* b2a = b2 + a * 400;
    const float* b3a = b3 + a * 100;

    float acc3[7][4];
    if (!isL2) {
        #pragma unroll
        for (int nt = 0; nt < 7; nt++) {
            int n = wn * 56 + nt * 8 + 2 * tg;
            float v0 = (n     < 100) ? __ldg(b3a + n)     : 0.0f;
            float v1 = (n + 1 < 100) ? __ldg(b3a + n + 1) : 0.0f;
            acc3[nt][0] = v0; acc3[nt][1] = v1; acc3[nt][2] = v0; acc3[nt][3] = v1;
        }
    }
    __syncthreads();    // h1 published

    // ---- pipelined main loop: L2 computes chunk c, L3 consumes chunk c-1 ----
    for (int c = 0; c < 5; c++) {
        if (isL2) {
            CP_WAIT0();      // W2(c) landed (this thread's cp)
            BAR1();          // visible to all L2 warps
            float acc2[5][4];
            #pragma unroll
            for (int nt = 0; nt < 5; nt++) {
                int n = 80 * c + wn * 40 + nt * 8 + 2 * tg;
                float v0 = __ldg(b2a + n), v1 = __ldg(b2a + n + 1);
                acc2[nt][0] = v0; acc2[nt][1] = v1; acc2[nt][2] = v0; acc2[nt][3] = v1;
            }
            #pragma unroll
            for (int ks = 0; ks < 7; ks++) {
                uint32_t aoff = (uint32_t)(((wm * 16 + lsel) * H1S + 16 * ks + csel) * 2);
                uint32_t a0, a1, a2, a3;
                ldsm4(h1_b + aoff, a0, a1, a2, a3);
                #pragma unroll
                for (int p = 0; p < 3; p++) {
                    uint32_t boff = (uint32_t)(((16 * ks + lsel) * W2S + wn * 40 + 16 * p + csel) * 2);
                    uint32_t bh0, bh1, bh2, bh3, bl0, bl1, bl2, bl3;
                    ldsm4t(w2h_b + boff, bh0, bh1, bh2, bh3);
                    ldsm4t(w2l_b + boff, bl0, bl1, bl2, bl3);
                    mma16816(acc2[2 * p], a0, a1, a2, a3, bh0, bh1);
                    mma16816(acc2[2 * p], a0, a1, a2, a3, bl0, bl1);
                    if (p < 2) {
                        mma16816(acc2[2 * p + 1], a0, a1, a2, a3, bh2, bh3);
                        mma16816(acc2[2 * p + 1], a0, a1, a2, a3, bl2, bl3);
                    }
                }
            }
            // relu -> h2[c&1] (single bf16, packed pair stores)
            __nv_bfloat16* s_h2 = (__nv_bfloat16*)(smraw + OFF_H2 + (c & 1) * H2B);
            #pragma unroll
            for (int nt = 0; nt < 5; nt++) {
                int n = wn * 40 + nt * 8 + 2 * tg;
                #pragma unroll
                for (int hh = 0; hh < 2; hh++) {
                    int row = wm * 16 + gg + 8 * hh;
                    __nv_bfloat162 pr;
                    pr.x = __float2bfloat16(fmaxf(acc2[nt][2 * hh + 0], 0.0f));
                    pr.y = __float2bfloat16(fmaxf(acc2[nt][2 * hh + 1], 0.0f));
                    *(__nv_bfloat162*)&s_h2[row * H2S + n] = pr;
                }
            }
            BAR1();          // all L2 done reading W2(c)
            if (c < 4) {     // stage W2(c+1)
                for (int i = gt; i < 1000; i += 512) {
                    int k = i / 10, q = i - k * 10;
                    uint32_t doff = (uint32_t)((k * W2S + 8 * q) * 2);
                    size_t soff = (size_t)k * 400 + 80 * (c + 1) + 8 * q;
                    cp16(w2h_b + doff, W2hp + soff);
                    cp16(w2l_b + doff, W2lp + soff);
                }
                CP_COMMIT();
            }
        } else {
            if (c > 0) {
                CP_WAIT0();  // W3(c-1) landed
                BAR2();
                uint32_t h2_b = sbase + OFF_H2 + ((c - 1) & 1) * H2B;
                #pragma unroll
                for (int ks = 0; ks < 5; ks++) {
                    uint32_t aoff = (uint32_t)(((wm * 16 + lsel) * H2S + 16 * ks + csel) * 2);
                    uint32_t a0, a1, a2, a3;
                    ldsm4(h2_b + aoff, a0, a1, a2, a3);
                    #pragma unroll
                    for (int p = 0; p < 4; p++) {
                        uint32_t boff = (uint32_t)(((16 * ks + lsel) * W3S + wn * 56 + 16 * p + csel) * 2);
                        uint32_t bh0, bh1, bh2, bh3, bl0, bl1, bl2, bl3;
                        ldsm4t(w3h_b + boff, bh0, bh1, bh2, bh3);
                        ldsm4t(w3l_b + boff, bl0, bl1, bl2, bl3);
                        mma16816(acc3[2 * p], a0, a1, a2, a3, bh0, bh1);
                        mma16816(acc3[2 * p], a0, a1, a2, a3, bl0, bl1);
                        if (p < 3) {
                            mma16816(acc3[2 * p + 1], a0, a1, a2, a3, bh2, bh3);
                            mma16816(acc3[2 * p + 1], a0, a1, a2, a3, bl2, bl3);
                        }
                    }
                }
                BAR2();      // all L3 done reading W3(c-1)
                // stage W3(c) (consumed next iteration / post-loop)
                for (int i = gt; i < 1120; i += 512) {
                    int k = i / 14, q = i - k * 14;
                    uint32_t doff = (uint32_t)((k * W3S + 8 * q) * 2);
                    size_t soff = (size_t)(80 * c + k) * 112 + 8 * q;
                    cp16(w3h_b + doff, W3hp + soff);
                    cp16(w3l_b + doff, W3lp + soff);
                }
                CP_COMMIT();
            }
        }
        __syncthreads();     // publish h2[c&1]; free h2[(c-1)&1]
    }

    // ---- drain: L3 consumes chunk 4 ----
    if (!isL2) {
        CP_WAIT0();
        BAR2();
        uint32_t h2_b = sbase + OFF_H2 + (4 & 1) * H2B;
        #pragma unroll
        for (int ks = 0; ks < 5; ks++) {
            uint32_t aoff = (uint32_t)(((wm * 16 + lsel) * H2S + 16 * ks + csel) * 2);
            uint32_t a0, a1, a2, a3;
            ldsm4(h2_b + aoff, a0, a1, a2, a3);
            #pragma unroll
            for (int p = 0; p < 4; p++) {
                uint32_t boff = (uint32_t)(((16 * ks + lsel) * W3S + wn * 56 + 16 * p + csel) * 2);
                uint32_t bh0, bh1, bh2, bh3, bl0, bl1, bl2, bl3;
                ldsm4t(w3h_b + boff, bh0, bh1, bh2, bh3);
                ldsm4t(w3l_b + boff, bl0, bl1, bl2, bl3);
                mma16816(acc3[2 * p], a0, a1, a2, a3, bh0, bh1);
                mma16816(acc3[2 * p], a0, a1, a2, a3, bl0, bl1);
                if (p < 3) {
                    mma16816(acc3[2 * p + 1], a0, a1, a2, a3, bh2, bh3);
                    mma16816(acc3[2 * p + 1], a0, a1, a2, a3, bl2, bl3);
                }
            }
        }
    }
    __syncthreads();         // all mma reads of weight bufs done

    // ---- h3 = relu(acc3) -> fp32 (over weight-stage region, now free) ----
    float* s_h3 = (float*)(smraw + OFF_W2H);    // 128*101*4 = 51.7KB
    if (!isL2) {
        #pragma unroll
        for (int nt = 0; nt < 7; nt++) {
            int n = wn * 56 + nt * 8 + 2 * tg;
            #pragma unroll
            for (int hh = 0; hh < 2; hh++) {
                int row = wm * 16 + gg + 8 * hh;
                if (n     < 100) s_h3[row * H3S + n]     = fmaxf(acc3[nt][2 * hh + 0], 0.0f);
                if (n + 1 < 100) s_h3[row * H3S + n + 1] = fmaxf(acc3[nt][2 * hh + 1], 0.0f);
            }
        }
    }
    __syncthreads();

    // ---- L4 + scatter fused: one thread per row, program-order stores ----
    if (t < TM) {
        int sid = s_sid[t];
        if (sid >= 0) {
            const float* W4a = W4 + a * 600;
            float acc[6];
            #pragma unroll
            for (int o = 0; o < 6; o++) acc[o] = __ldg(b4 + a * 6 + o);
            #pragma unroll 4
            for (int k = 0; k < 100; k++) {
                float h = s_h3[t * H3S + k];
                #pragma unroll
                for (int o = 0; o < 6; o++) acc[o] += h * __ldg(W4a + k * 6 + o);
            }
            size_t rb = (size_t)sid * XX;
            int b6 = sid * 6;
            #pragma unroll
            for (int j = 0; j < 6; j++)
                out[rb + g_idx[b6 + j]] = g_att[b6 + j] + acc[j];
        }
    }
}

// ---------------- launch ----------------
extern "C" void kernel_launch(void* const* d_in, const int* in_sizes, int n_in,
                              void* d_out, int out_size) {
    const float* x  = (const float*)d_in[0];
    const float* W1 = (const float*)d_in[1];
    const float* b1 = (const float*)d_in[2];
    const float* W2 = (const float*)d_in[3];
    const float* b2 = (const float*)d_in[4];
    const float* W3 = (const float*)d_in[5];
    const float* b3 = (const float*)d_in[6];
    const float* W4 = (const float*)d_in[7];
    const float* b4 = (const float*)d_in[8];
    const int*   ba = (const int*)d_in[9];
    float* out = (float*)d_out;

    cudaFuncSetAttribute(k_mlp, cudaFuncAttributeMaxDynamicSharedMemorySize, SMEM_TOT);

    k_convw<<<(3 * 400 * 112 + 255) / 256, 256>>>(W2, W3);
    k_prep<<<BB / 8, 256>>>(x, out);
    k_assign<<<BB / 256, 256>>>(ba);
    dim3 g((BB + TM - 1) / TM, 3);
    k_mlp<<<g, 1024, SMEM_TOT>>>(W1, b1, b2, b3, W4, b4, out);
}

// round 9
// speedup vs baseline: 7.9567x; 1.2414x over previous
#include <cuda_runtime.h>
#include <cuda_bf16.h>
#include <cstdint>

#define BB 65536
#define XX 362
#define TM 128

#define H1S 120   // h1 bf16 row stride (100 real, zero pad to 112+)
#define H2S 88    // h2 bf16 row stride (80 real)
#define W2S 88    // W2 stage stride: 112 k-rows x 88 (80 real n)
#define W3S 120   // W3 stage stride: 80 k-rows x 120 (112 real n)
#define H3S 101

// smem byte offsets (16B aligned)
#define OFF_H1   0         // 30720
#define OFF_H2   30720     // 2 x 22528
#define H2B      22528
#define OFF_W2   75776     // 19712
#define OFF_W3   95488     // 19200
#define OFF_ATT  114688    // 4096
#define OFF_SID  118784    // 512
#define SMEM_TOT 119296

// ---------------- scratch ----------------
__device__ float g_att [BB * 6];
__device__ int   g_idx [BB * 6];
__device__ int   g_order[3 * BB];
__device__ int   g_cnt [3];
__device__ __align__(16) __nv_bfloat16 g_w2[3 * 40000];        // [a][100][400]
__device__ __align__(16) __nv_bfloat16 g_w3[3 * 400 * 112];    // [a][400][112 pad]

// ---------------- helpers ----------------
__device__ __forceinline__ uint32_t smaddr(const void* p) {
    return (uint32_t)__cvta_generic_to_shared(p);
}
__device__ __forceinline__ void ldsm4(uint32_t a, uint32_t& r0, uint32_t& r1,
                                      uint32_t& r2, uint32_t& r3) {
    asm volatile("ldmatrix.sync.aligned.m8n8.x4.shared.b16 {%0,%1,%2,%3},[%4];"
                 : "=r"(r0), "=r"(r1), "=r"(r2), "=r"(r3) : "r"(a));
}
__device__ __forceinline__ void ldsm4t(uint32_t a, uint32_t& r0, uint32_t& r1,
                                       uint32_t& r2, uint32_t& r3) {
    asm volatile("ldmatrix.sync.aligned.m8n8.x4.trans.shared.b16 {%0,%1,%2,%3},[%4];"
                 : "=r"(r0), "=r"(r1), "=r"(r2), "=r"(r3) : "r"(a));
}
__device__ __forceinline__ void mma16816(float (&d)[4], uint32_t a0, uint32_t a1,
                                         uint32_t a2, uint32_t a3,
                                         uint32_t b0, uint32_t b1) {
    asm volatile(
        "mma.sync.aligned.m16n8k16.row.col.f32.bf16.bf16.f32 "
        "{%0,%1,%2,%3},{%4,%5,%6,%7},{%8,%9},{%0,%1,%2,%3};"
        : "+f"(d[0]), "+f"(d[1]), "+f"(d[2]), "+f"(d[3])
        : "r"(a0), "r"(a1), "r"(a2), "r"(a3), "r"(b0), "r"(b1));
}
__device__ __forceinline__ void cp16(uint32_t dst, const void* src) {
    asm volatile("cp.async.cg.shared.global [%0], [%1], 16;" :: "r"(dst), "l"(src));
}
#define CP_COMMIT() asm volatile("cp.async.commit_group;")
#define CP_WAIT0()  asm volatile("cp.async.wait_group 0;")
#define BAR1() asm volatile("bar.sync 1, 512;" ::: "memory")
#define BAR2() asm volatile("bar.sync 2, 512;" ::: "memory")

// ---------------- 0: weights -> bf16 (+ reset counters) ----------------
__global__ void k_convw(const float* __restrict__ W2, const float* __restrict__ W3) {
    int i = blockIdx.x * 256 + threadIdx.x;
    if (blockIdx.x == 0 && threadIdx.x < 3) g_cnt[threadIdx.x] = 0;
    if (i < 3 * 40000) g_w2[i] = __float2bfloat16(W2[i]);
    if (i < 3 * 400 * 112) {
        int an = i / 44800, r = (i % 44800) / 112, c = i % 112;
        g_w3[i] = __float2bfloat16((c < 100) ? W3[an * 40000 + r * 100 + c] : 0.0f);
    }
}

// ---------------- 1: copy + argmax + gather ----------------
__global__ void k_prep(const float* __restrict__ x, float* __restrict__ out) {
    int row  = blockIdx.x * 8 + (threadIdx.x >> 5);
    int lane = threadIdx.x & 31;
    const float* xr = x   + (size_t)row * XX;
    float*     orow = out + (size_t)row * XX;

    float bv = -3.4e38f;
    int   bi = 0;
    for (int i = lane; i < XX; i += 32) {
        float v = xr[i];
        orow[i] = v;
        if (v > bv) { bv = v; bi = i; }
    }
    #pragma unroll
    for (int off = 16; off > 0; off >>= 1) {
        float ov = __shfl_down_sync(0xffffffffu, bv, off);
        int   oi = __shfl_down_sync(0xffffffffu, bi, off);
        if (ov > bv || (ov == bv && oi < bi)) { bv = ov; bi = oi; }
    }
    int ptr = __shfl_sync(0xffffffffu, bi, 0);

    if (lane < 6) {
        int idx;
        if      (lane == 0) idx = 0;
        else if (lane == 1) idx = ptr;                 // unclamped, as in source
        else {
            int d = (lane == 2) ? -19 : (lane == 3) ? 19 : (lane == 4) ? -1 : 1;
            idx = ptr + d;
            idx = idx < 1 ? 1 : (idx > XX - 1 ? XX - 1 : idx);
        }
        g_idx[row * 6 + lane] = idx;
        g_att[row * 6 + lane] = xr[idx];
    }
}

// ---------------- 2: group samples by action ----------------
__global__ void k_assign(const int* __restrict__ ba) {
    int i = blockIdx.x * blockDim.x + threadIdx.x;
    int a = ba[i];
    unsigned full = 0xffffffffu;
    unsigned m0 = __ballot_sync(full, a == 0);
    unsigned m1 = __ballot_sync(full, a == 1);
    unsigned m2 = __ballot_sync(full, a == 2);
    unsigned mk = (a == 0) ? m0 : (a == 1) ? m1 : m2;
    int lane   = threadIdx.x & 31;
    int leader = (int)__ffs(mk) - 1;
    int rank   = __popc(mk & ((1u << lane) - 1u));
    int pos    = 0;
    if (lane == leader) pos = atomicAdd(&g_cnt[a], __popc(mk));
    pos = __shfl_sync(full, pos, leader);
    g_order[a * BB + pos + rank] = i;
}

// ---------------- 3: warp-specialized MLP (single-bf16 operands) ---------
__global__ void __launch_bounds__(1024, 1) k_mlp(
    const float* __restrict__ W1, const float* __restrict__ b1,
    const float* __restrict__ b2, const float* __restrict__ b3,
    const float* __restrict__ W4, const float* __restrict__ b4,
    float* __restrict__ out)
{
    int a   = blockIdx.y;
    int cnt = g_cnt[a];
    int m0b = blockIdx.x * TM;
    if (m0b >= cnt) return;
    int M = min(TM, cnt - m0b);

    extern __shared__ char smraw[];
    __nv_bfloat16* s_h1  = (__nv_bfloat16*)(smraw + OFF_H1);
    float*         s_att = (float*)(smraw + OFF_ATT);
    int*           s_sid = (int*)(smraw + OFF_SID);

    const __nv_bfloat16* W2p = g_w2 + a * 40000;
    const __nv_bfloat16* W3p = g_w3 + a * 44800;

    uint32_t sbase = smaddr(smraw);
    uint32_t h1_b = sbase + OFF_H1;
    uint32_t w2_b = sbase + OFF_W2;
    uint32_t w3_b = sbase + OFF_W3;

    int t    = threadIdx.x;
    int lane = t & 31;
    int warp = t >> 5;
    bool isL2 = warp < 16;
    int gt   = isL2 ? t : (t - 512);
    int gw   = warp & 15;
    int wm   = gw & 7;            // 8 m-tiles of 16 rows
    int wn   = gw >> 3;           // 2 n-halves
    int tg   = lane & 3;
    int gg   = lane >> 2;
    int lsel = lane & 15;
    int csel = (lane >> 4) * 8;

    // ---- prologue ----
    if (t < TM) s_sid[t] = (t < M) ? g_order[a * BB + m0b + t] : -1;

    if (isL2) {
        for (int i = gt; i < 1000; i += 512) {         // stage W2(0)
            int k = i / 10, q = i - k * 10;
            cp16(w2_b + (uint32_t)((k * W2S + 8 * q) * 2), W2p + (size_t)k * 400 + 8 * q);
        }
        CP_COMMIT();
        for (int i = gt; i < 528; i += 512)            // zero W2 k-pad rows 100..111
            ((uint32_t*)(smraw + OFF_W2))[4400 + i] = 0;
    } else {
        for (int i = gt; i < 1120; i += 512) {         // stage W3(0)
            int k = i / 14, q = i - k * 14;
            cp16(w3_b + (uint32_t)((k * W3S + 8 * q) * 2), W3p + (size_t)k * 112 + 8 * q);
        }
        CP_COMMIT();
    }
    __syncthreads();

    for (int i = t; i < TM * 6; i += 1024) {
        int m = i / 6, j = i - m * 6;
        int sid = s_sid[m];
        s_att[m * 8 + j] = (sid >= 0) ? g_att[sid * 6 + j] : 0.0f;
    }
    __syncthreads();

    // ---- L1 (fp32): h1 = relu(att@W1+b1) -> bf16, zero pad ----
    {
        const float* W1a = W1 + a * 600;
        const float* b1a = b1 + a * 100;
        for (int i = t; i < TM * H1S; i += 1024) {
            int m = i / H1S, n = i - m * H1S;
            float v = 0.0f;
            if (n < 100) {
                v = __ldg(b1a + n);
                #pragma unroll
                for (int k = 0; k < 6; k++) v += s_att[m * 8 + k] * __ldg(W1a + k * 100 + n);
                v = fmaxf(v, 0.0f);
            }
            s_h1[i] = __float2bfloat16(v);
        }
    }

    const float* b2a = b2 + a * 400;
    const float* b3a = b3 + a * 100;

    float acc3[7][4];
    if (!isL2) {
        #pragma unroll
        for (int nt = 0; nt < 7; nt++) {
            int n = wn * 56 + nt * 8 + 2 * tg;
            float v0 = (n     < 100) ? __ldg(b3a + n)     : 0.0f;
            float v1 = (n + 1 < 100) ? __ldg(b3a + n + 1) : 0.0f;
            acc3[nt][0] = v0; acc3[nt][1] = v1; acc3[nt][2] = v0; acc3[nt][3] = v1;
        }
    }
    __syncthreads();    // h1 published

    // ---- pipelined main loop: L2 computes chunk c, L3 consumes chunk c-1 --
    for (int c = 0; c < 5; c++) {
        if (isL2) {
            CP_WAIT0();
            BAR1();
            float acc2[5][4];
            #pragma unroll
            for (int nt = 0; nt < 5; nt++) {
                int n = 80 * c + wn * 40 + nt * 8 + 2 * tg;
                float v0 = __ldg(b2a + n), v1 = __ldg(b2a + n + 1);
                acc2[nt][0] = v0; acc2[nt][1] = v1; acc2[nt][2] = v0; acc2[nt][3] = v1;
            }
            #pragma unroll
            for (int ks = 0; ks < 7; ks++) {
                uint32_t aoff = (uint32_t)(((wm * 16 + lsel) * H1S + 16 * ks + csel) * 2);
                uint32_t a0, a1, a2, a3;
                ldsm4(h1_b + aoff, a0, a1, a2, a3);
                #pragma unroll
                for (int p = 0; p < 3; p++) {
                    uint32_t boff = (uint32_t)(((16 * ks + lsel) * W2S + wn * 40 + 16 * p + csel) * 2);
                    uint32_t b0, b1v, b2v, b3v;
                    ldsm4t(w2_b + boff, b0, b1v, b2v, b3v);
                    mma16816(acc2[2 * p], a0, a1, a2, a3, b0, b1v);
                    if (p < 2) mma16816(acc2[2 * p + 1], a0, a1, a2, a3, b2v, b3v);
                }
            }
            // relu -> h2[c&1]
            __nv_bfloat16* s_h2 = (__nv_bfloat16*)(smraw + OFF_H2 + (c & 1) * H2B);
            #pragma unroll
            for (int nt = 0; nt < 5; nt++) {
                int n = wn * 40 + nt * 8 + 2 * tg;
                #pragma unroll
                for (int hh = 0; hh < 2; hh++) {
                    int row = wm * 16 + gg + 8 * hh;
                    __nv_bfloat162 pr;
                    pr.x = __float2bfloat16(fmaxf(acc2[nt][2 * hh + 0], 0.0f));
                    pr.y = __float2bfloat16(fmaxf(acc2[nt][2 * hh + 1], 0.0f));
                    *(__nv_bfloat162*)&s_h2[row * H2S + n] = pr;
                }
            }
            BAR1();
            if (c < 4) {
                for (int i = gt; i < 1000; i += 512) {   // stage W2(c+1)
                    int k = i / 10, q = i - k * 10;
                    cp16(w2_b + (uint32_t)((k * W2S + 8 * q) * 2),
                         W2p + (size_t)k * 400 + 80 * (c + 1) + 8 * q);
                }
                CP_COMMIT();
            }
        } else {
            if (c > 0) {
                CP_WAIT0();
                BAR2();
                uint32_t h2_b = sbase + OFF_H2 + ((c - 1) & 1) * H2B;
                #pragma unroll
                for (int ks = 0; ks < 5; ks++) {
                    uint32_t aoff = (uint32_t)(((wm * 16 + lsel) * H2S + 16 * ks + csel) * 2);
                    uint32_t a0, a1, a2, a3;
                    ldsm4(h2_b + aoff, a0, a1, a2, a3);
                    #pragma unroll
                    for (int p = 0; p < 4; p++) {
                        uint32_t boff = (uint32_t)(((16 * ks + lsel) * W3S + wn * 56 + 16 * p + csel) * 2);
                        uint32_t b0, b1v, b2v, b3v;
                        ldsm4t(w3_b + boff, b0, b1v, b2v, b3v);
                        mma16816(acc3[2 * p], a0, a1, a2, a3, b0, b1v);
                        if (p < 3) mma16816(acc3[2 * p + 1], a0, a1, a2, a3, b2v, b3v);
                    }
                }
                BAR2();
                for (int i = gt; i < 1120; i += 512) {   // stage W3(c)
                    int k = i / 14, q = i - k * 14;
                    cp16(w3_b + (uint32_t)((k * W3S + 8 * q) * 2),
                         W3p + (size_t)(80 * c + k) * 112 + 8 * q);
                }
                CP_COMMIT();
            }
        }
        __syncthreads();     // publish h2[c&1]; free h2[(c-1)&1]
    }

    // ---- drain: L3 consumes chunk 4 ----
    if (!isL2) {
        CP_WAIT0();
        BAR2();
        uint32_t h2_b = sbase + OFF_H2 + (4 & 1) * H2B;
        #pragma unroll
        for (int ks = 0; ks < 5; ks++) {
            uint32_t aoff = (uint32_t)(((wm * 16 + lsel) * H2S + 16 * ks + csel) * 2);
            uint32_t a0, a1, a2, a3;
            ldsm4(h2_b + aoff, a0, a1, a2, a3);
            #pragma unroll
            for (int p = 0; p < 4; p++) {
                uint32_t boff = (uint32_t)(((16 * ks + lsel) * W3S + wn * 56 + 16 * p + csel) * 2);
                uint32_t b0, b1v, b2v, b3v;
                ldsm4t(w3_b + boff, b0, b1v, b2v, b3v);
                mma16816(acc3[2 * p], a0, a1, a2, a3, b0, b1v);
                if (p < 3) mma16816(acc3[2 * p + 1], a0, a1, a2, a3, b2v, b3v);
            }
        }
    }
    __syncthreads();

    // ---- h3 = relu(acc3) -> fp32 (over W2 stage region, now free) ----
    float* s_h3 = (float*)(smraw + OFF_H1);     // 128*101*4 = 51.7KB over h1/h2 region
    if (!isL2) {
        #pragma unroll
        for (int nt = 0; nt < 7; nt++) {
            int n = wn * 56 + nt * 8 + 2 * tg;
            #pragma unroll
            for (int hh = 0; hh < 2; hh++) {
                int row = wm * 16 + gg + 8 * hh;
                if (n     < 100) s_h3[row * H3S + n]     = fmaxf(acc3[nt][2 * hh + 0], 0.0f);
                if (n + 1 < 100) s_h3[row * H3S + n + 1] = fmaxf(acc3[nt][2 * hh + 1], 0.0f);
            }
        }
    }
    __syncthreads();

    // ---- L4 + scatter fused: one thread per row, program-order stores ----
    if (t < TM) {
        int sid = s_sid[t];
        if (sid >= 0) {
            const float* W4a = W4 + a * 600;
            float acc[6];
            #pragma unroll
            for (int o = 0; o < 6; o++) acc[o] = __ldg(b4 + a * 6 + o);
            #pragma unroll 4
            for (int k = 0; k < 100; k++) {
                float h = s_h3[t * H3S + k];
                #pragma unroll
                for (int o = 0; o < 6; o++) acc[o] += h * __ldg(W4a + k * 6 + o);
            }
            size_t rb = (size_t)sid * XX;
            int b6 = sid * 6;
            #pragma unroll
            for (int j = 0; j < 6; j++)
                out[rb + g_idx[b6 + j]] = g_att[b6 + j] + acc[j];
        }
    }
}

// ---------------- launch ----------------
extern "C" void kernel_launch(void* const* d_in, const int* in_sizes, int n_in,
                              void* d_out, int out_size) {
    const float* x  = (const float*)d_in[0];
    const float* W1 = (const float*)d_in[1];
    const float* b1 = (const float*)d_in[2];
    const float* W2 = (const float*)d_in[3];
    const float* b2 = (const float*)d_in[4];
    const float* W3 = (const float*)d_in[5];
    const float* b3 = (const float*)d_in[6];
    const float* W4 = (const float*)d_in[7];
    const float* b4 = (const float*)d_in[8];
    const int*   ba = (const int*)d_in[9];
    float* out = (float*)d_out;

    cudaFuncSetAttribute(k_mlp, cudaFuncAttributeMaxDynamicSharedMemorySize, SMEM_TOT);

    k_convw<<<(3 * 400 * 112 + 255) / 256, 256>>>(W2, W3);
    k_prep<<<BB / 8, 256>>>(x, out);
    k_assign<<<BB / 256, 256>>>(ba);
    dim3 g((BB + TM - 1) / TM, 3);
    k_mlp<<<g, 1024, SMEM_TOT>>>(W1, b1, b2, b3, W4, b4, out);
}

// round 11
// speedup vs baseline: 9.6115x; 1.2080x over previous
#include <cuda_runtime.h>
#include <cuda_bf16.h>
#include <cstdint>

#define BB 65536
#define XX 362
#define TM 64

#define H1S 120
#define H2S 88
#define W2S 88
#define W3S 120
#define W1S 120
#define ATTBS 24
#define H3S 101

// smem byte offsets (16B aligned)
#define OFF_H1   0        // 15360
#define OFF_H2   15360    // 2 x 11264
#define H2B      11264
#define OFF_W2   37888    // 19712
#define OFF_W3   57600    // 19200
#define OFF_W1B  76800    // 3840
#define OFF_ATTB 80640    // 3072
#define OFF_ATT  83712    // 2048
#define OFF_IDX  85760    // 2048
#define OFF_BIAS 87808    // 2000 (b1[100] b2[400])
#define OFF_W4   89808    // 2400
#define OFF_SID  92208    // 256
#define SMEM_TOT 92464

#define NBLK 3072         // 1024 x 3

// ---------------- scratch ----------------
__device__ int   g_order[3 * BB];
__device__ int   g_cnt [3];
__device__ int   g_done;
__device__ __align__(16) __nv_bfloat16 g_w2[3 * 40000];       // [a][100][400]
__device__ __align__(16) __nv_bfloat16 g_w3[3 * 400 * 112];   // [a][400][112]
__device__ __align__(16) __nv_bfloat16 g_w1b[3 * 16 * 112];   // [a][16][112] zero-pad

// ---------------- helpers ----------------
__device__ __forceinline__ uint32_t smaddr(const void* p) {
    return (uint32_t)__cvta_generic_to_shared(p);
}
__device__ __forceinline__ void ldsm4(uint32_t a, uint32_t& r0, uint32_t& r1,
                                      uint32_t& r2, uint32_t& r3) {
    asm volatile("ldmatrix.sync.aligned.m8n8.x4.shared.b16 {%0,%1,%2,%3},[%4];"
                 : "=r"(r0), "=r"(r1), "=r"(r2), "=r"(r3) : "r"(a));
}
__device__ __forceinline__ void ldsm4t(uint32_t a, uint32_t& r0, uint32_t& r1,
                                       uint32_t& r2, uint32_t& r3) {
    asm volatile("ldmatrix.sync.aligned.m8n8.x4.trans.shared.b16 {%0,%1,%2,%3},[%4];"
                 : "=r"(r0), "=r"(r1), "=r"(r2), "=r"(r3) : "r"(a));
}
__device__ __forceinline__ void mma16816(float (&d)[4], uint32_t a0, uint32_t a1,
                                         uint32_t a2, uint32_t a3,
                                         uint32_t b0, uint32_t b1) {
    asm volatile(
        "mma.sync.aligned.m16n8k16.row.col.f32.bf16.bf16.f32 "
        "{%0,%1,%2,%3},{%4,%5,%6,%7},{%8,%9},{%0,%1,%2,%3};"
        : "+f"(d[0]), "+f"(d[1]), "+f"(d[2]), "+f"(d[3])
        : "r"(a0), "r"(a1), "r"(a2), "r"(a3), "r"(b0), "r"(b1));
}
__device__ __forceinline__ void cp16(uint32_t dst, const void* src) {
    asm volatile("cp.async.cg.shared.global [%0], [%1], 16;" :: "r"(dst), "l"(src));
}
#define CP_COMMIT() asm volatile("cp.async.commit_group;")
#define CP_WAIT0()  asm volatile("cp.async.wait_group 0;")
#define BAR1() asm volatile("bar.sync 1, 256;" ::: "memory")
#define BAR2() asm volatile("bar.sync 2, 256;" ::: "memory")

// ---------------- 0: fused weight-convert + action grouping --------------
__global__ void k_pre(const float* __restrict__ W1, const float* __restrict__ W2,
                      const float* __restrict__ W3, const int* __restrict__ ba) {
    int b = blockIdx.x;
    if (b < 525) {
        int i = b * 256 + threadIdx.x;
        if (i < 120000) g_w2[i] = __float2bfloat16(W2[i]);
        if (i < 134400) {
            int an = i / 44800, r = (i % 44800) / 112, c = i % 112;
            g_w3[i] = __float2bfloat16((c < 100) ? W3[an * 40000 + r * 100 + c] : 0.0f);
        }
        if (i < 5376) {
            int an = i / 1792, rem = i % 1792, r = rem / 112, c = rem % 112;
            g_w1b[i] = __float2bfloat16((r < 6 && c < 100) ? W1[an * 600 + r * 100 + c] : 0.0f);
        }
    } else {
        int i = (b - 525) * 256 + threadIdx.x;
        int a = ba[i];
        unsigned full = 0xffffffffu;
        unsigned m0 = __ballot_sync(full, a == 0);
        unsigned m1 = __ballot_sync(full, a == 1);
        unsigned m2 = __ballot_sync(full, a == 2);
        unsigned mk = (a == 0) ? m0 : (a == 1) ? m1 : m2;
        int lane   = threadIdx.x & 31;
        int leader = (int)__ffs(mk) - 1;
        int rank   = __popc(mk & ((1u << lane) - 1u));
        int pos    = 0;
        if (lane == leader) pos = atomicAdd(&g_cnt[a], __popc(mk));
        pos = __shfl_sync(full, pos, leader);
        g_order[a * BB + pos + rank] = i;
    }
}

// ---------------- 1: fused prep + MLP + scatter, 2 blocks/SM --------------
__global__ void __launch_bounds__(512, 2) k_mlp(
    const float* __restrict__ x,
    const float* __restrict__ b1, const float* __restrict__ b2,
    const float* __restrict__ b3, const float* __restrict__ W4,
    const float* __restrict__ b4, float* __restrict__ out)
{
    int a   = blockIdx.y;
    int cnt = g_cnt[a];
    int m0b = blockIdx.x * TM;

    if (m0b < cnt) {
    int M = min(TM, cnt - m0b);

    extern __shared__ char smraw[];
    __nv_bfloat16* s_h1   = (__nv_bfloat16*)(smraw + OFF_H1);
    __nv_bfloat16* s_attb = (__nv_bfloat16*)(smraw + OFF_ATTB);
    float*         s_att  = (float*)(smraw + OFF_ATT);
    int*           s_idx  = (int*)(smraw + OFF_IDX);
    float*         s_bias = (float*)(smraw + OFF_BIAS);   // [0..99]=b1, [100..499]=b2
    float*         s_w4   = (float*)(smraw + OFF_W4);
    int*           s_sid  = (int*)(smraw + OFF_SID);

    const __nv_bfloat16* W2p = g_w2 + a * 40000;
    const __nv_bfloat16* W3p = g_w3 + a * 44800;

    uint32_t sbase  = smaddr(smraw);
    uint32_t h1_b   = sbase + OFF_H1;
    uint32_t w2_b   = sbase + OFF_W2;
    uint32_t w3_b   = sbase + OFF_W3;
    uint32_t w1b_b  = sbase + OFF_W1B;
    uint32_t attb_b = sbase + OFF_ATTB;
    uint32_t bias_b = sbase + OFF_BIAS;
    uint32_t w4_b   = sbase + OFF_W4;

    int t    = threadIdx.x;
    int lane = t & 31;
    int warp = t >> 5;
    bool isL2 = warp < 8;
    int gt   = isL2 ? t : (t - 256);
    int gw   = warp & 7;
    int wm   = gw & 3;            // 4 m-tiles of 16 rows
    int wn   = gw >> 2;           // 2 n-halves
    int tg   = lane & 3;
    int gg   = lane >> 2;
    int lsel = lane & 15;
    int csel = (lane >> 4) * 8;

    if (t < TM) s_sid[t] = (t < M) ? g_order[a * BB + m0b + t] : -1;

    // ---- cp.async prologue: weights chunk 0 + W1b + biases + W4 ----
    if (isL2) {
        for (int i = gt; i < 1000; i += 256) {          // W2(0)
            int k = i / 10, q = i - k * 10;
            cp16(w2_b + (uint32_t)((k * W2S + 8 * q) * 2), W2p + (size_t)k * 400 + 8 * q);
        }
        for (int i = gt; i < 224; i += 256) {           // W1b
            int r = i / 14, q = i - r * 14;
            cp16(w1b_b + (uint32_t)((r * W1S + 8 * q) * 2), g_w1b + a * 1792 + r * 112 + 8 * q);
        }
        for (int i = gt; i < 25;  i += 256) cp16(bias_b + i * 16,       b1 + a * 100 + i * 4);
        for (int i = gt; i < 100; i += 256) cp16(bias_b + 400 + i * 16, b2 + a * 400 + i * 4);
        for (int i = gt; i < 150; i += 256) cp16(w4_b + i * 16,         W4 + a * 600 + i * 4);
        CP_COMMIT();
        for (int i = gt; i < 528; i += 256)             // zero W2 k-pad rows 100..111
            ((uint32_t*)(smraw + OFF_W2))[4400 + i] = 0;
    } else {
        for (int i = gt; i < 1120; i += 256) {          // W3(0)
            int k = i / 14, q = i - k * 14;
            cp16(w3_b + (uint32_t)((k * W3S + 8 * q) * 2), W3p + (size_t)k * 112 + 8 * q);
        }
        CP_COMMIT();
    }
    __syncthreads();    // s_sid visible

    // ---- copy + argmax + gather: each warp owns 4 rows ----
    #pragma unroll 1
    for (int j = 0; j < 4; j++) {
        int r   = warp * 4 + j;
        int sid = s_sid[r];
        if (sid >= 0) {
            const float2* xp = (const float2*)(x   + (size_t)sid * XX);
            float2*       op = (float2*)      (out + (size_t)sid * XX);
            float bv = -3.4e38f;
            int   bi = 0;
            for (int i = lane; i < 181; i += 32) {
                float2 v = xp[i];
                op[i] = v;
                if (v.x > bv) { bv = v.x; bi = 2 * i; }
                if (v.y > bv) { bv = v.y; bi = 2 * i + 1; }
            }
            #pragma unroll
            for (int off = 16; off > 0; off >>= 1) {
                float ov = __shfl_down_sync(0xffffffffu, bv, off);
                int   oi = __shfl_down_sync(0xffffffffu, bi, off);
                if (ov > bv || (ov == bv && oi < bi)) { bv = ov; bi = oi; }
            }
            int ptr = __shfl_sync(0xffffffffu, bi, 0);
            if (lane < 16) {
                if (lane < 6) {
                    int idx;
                    if      (lane == 0) idx = 0;
                    else if (lane == 1) idx = ptr;      // unclamped, as in source
                    else {
                        int d = (lane == 2) ? -19 : (lane == 3) ? 19 : (lane == 4) ? -1 : 1;
                        idx = ptr + d;
                        idx = idx < 1 ? 1 : (idx > XX - 1 ? XX - 1 : idx);
                    }
                    float v = __ldg(x + (size_t)sid * XX + idx);
                    s_att[r * 8 + lane]     = v;
                    s_idx[r * 8 + lane]     = idx;
                    s_attb[r * ATTBS + lane] = __float2bfloat16(v);
                } else {
                    s_attb[r * ATTBS + lane] = __float2bfloat16(0.0f);
                }
            }
        } else {
            if (lane < 16) s_attb[r * ATTBS + lane] = __float2bfloat16(0.0f);
        }
    }
    __syncthreads();    // attb ready

    float acc3[7][4];

    // ---- L1 via MMA (L2 warps): h1 = relu(attb @ W1b + b1) ----
    if (isL2) {
        CP_WAIT0();     // G0: W2(0), W1b, biases, W4
        BAR1();
        float acc1[7][4];
        #pragma unroll
        for (int nt = 0; nt < 7; nt++) {
            int n = wn * 56 + nt * 8 + 2 * tg;
            float v0 = (n     < 100) ? s_bias[n]     : 0.0f;
            float v1 = (n + 1 < 100) ? s_bias[n + 1] : 0.0f;
            acc1[nt][0] = v0; acc1[nt][1] = v1; acc1[nt][2] = v0; acc1[nt][3] = v1;
        }
        uint32_t aoff = (uint32_t)(((wm * 16 + lsel) * ATTBS + csel) * 2);
        uint32_t a0, a1, a2, a3;
        ldsm4(attb_b + aoff, a0, a1, a2, a3);
        #pragma unroll
        for (int p = 0; p < 4; p++) {
            uint32_t boff = (uint32_t)((lsel * W1S + wn * 56 + 16 * p + csel) * 2);
            uint32_t b0v, b1v, b2v, b3v;
            ldsm4t(w1b_b + boff, b0v, b1v, b2v, b3v);
            mma16816(acc1[2 * p], a0, a1, a2, a3, b0v, b1v);
            if (p < 3) mma16816(acc1[2 * p + 1], a0, a1, a2, a3, b2v, b3v);
        }
        #pragma unroll
        for (int nt = 0; nt < 7; nt++) {
            int n = wn * 56 + nt * 8 + 2 * tg;
            #pragma unroll
            for (int hh = 0; hh < 2; hh++) {
                int row = wm * 16 + gg + 8 * hh;
                __nv_bfloat162 pr;
                pr.x = __float2bfloat16(fmaxf(acc1[nt][2 * hh + 0], 0.0f));
                pr.y = __float2bfloat16(fmaxf(acc1[nt][2 * hh + 1], 0.0f));
                *(__nv_bfloat162*)&s_h1[row * H1S + n] = pr;
            }
        }
        BAR1();         // h1 ready across L2 warps
    } else {
        const float* b3a = b3 + a * 100;
        #pragma unroll
        for (int nt = 0; nt < 7; nt++) {
            int n = wn * 56 + nt * 8 + 2 * tg;
            float v0 = (n     < 100) ? __ldg(b3a + n)     : 0.0f;
            float v1 = (n + 1 < 100) ? __ldg(b3a + n + 1) : 0.0f;
            acc3[nt][0] = v0; acc3[nt][1] = v1; acc3[nt][2] = v0; acc3[nt][3] = v1;
        }
    }

    // ---- main loop: L2 computes chunk c, L3 consumes chunk c-1 ----
    for (int c = 0; c < 5; c++) {
        if (isL2) {
            CP_WAIT0();
            BAR1();
            float acc2[5][4];
            #pragma unroll
            for (int nt = 0; nt < 5; nt++) {
                int n = 80 * c + wn * 40 + nt * 8 + 2 * tg;
                float v0 = s_bias[100 + n], v1 = s_bias[101 + n];
                acc2[nt][0] = v0; acc2[nt][1] = v1; acc2[nt][2] = v0; acc2[nt][3] = v1;
            }
            #pragma unroll
            for (int ks = 0; ks < 7; ks++) {
                uint32_t aoff = (uint32_t)(((wm * 16 + lsel) * H1S + 16 * ks + csel) * 2);
                uint32_t a0, a1, a2, a3;
                ldsm4(h1_b + aoff, a0, a1, a2, a3);
                #pragma unroll
                for (int p = 0; p < 3; p++) {
                    uint32_t boff = (uint32_t)(((16 * ks + lsel) * W2S + wn * 40 + 16 * p + csel) * 2);
                    uint32_t b0v, b1v, b2v, b3v;
                    ldsm4t(w2_b + boff, b0v, b1v, b2v, b3v);
                    mma16816(acc2[2 * p], a0, a1, a2, a3, b0v, b1v);
                    if (p < 2) mma16816(acc2[2 * p + 1], a0, a1, a2, a3, b2v, b3v);
                }
            }
            __nv_bfloat16* s_h2 = (__nv_bfloat16*)(smraw + OFF_H2 + (c & 1) * H2B);
            #pragma unroll
            for (int nt = 0; nt < 5; nt++) {
                int n = wn * 40 + nt * 8 + 2 * tg;
                #pragma unroll
                for (int hh = 0; hh < 2; hh++) {
                    int row = wm * 16 + gg + 8 * hh;
                    __nv_bfloat162 pr;
                    pr.x = __float2bfloat16(fmaxf(acc2[nt][2 * hh + 0], 0.0f));
                    pr.y = __float2bfloat16(fmaxf(acc2[nt][2 * hh + 1], 0.0f));
                    *(__nv_bfloat162*)&s_h2[row * H2S + n] = pr;
                }
            }
            BAR1();
            if (c < 4) {
                for (int i = gt; i < 1000; i += 256) {
                    int k = i / 10, q = i - k * 10;
                    cp16(w2_b + (uint32_t)((k * W2S + 8 * q) * 2),
                         W2p + (size_t)k * 400 + 80 * (c + 1) + 8 * q);
                }
                CP_COMMIT();
            }
        } else {
            if (c > 0) {
                CP_WAIT0();
                BAR2();
                uint32_t h2_b = sbase + OFF_H2 + ((c - 1) & 1) * H2B;
                #pragma unroll
                for (int ks = 0; ks < 5; ks++) {
                    uint32_t aoff = (uint32_t)(((wm * 16 + lsel) * H2S + 16 * ks + csel) * 2);
                    uint32_t a0, a1, a2, a3;
                    ldsm4(h2_b + aoff, a0, a1, a2, a3);
                    #pragma unroll
                    for (int p = 0; p < 4; p++) {
                        uint32_t boff = (uint32_t)(((16 * ks + lsel) * W3S + wn * 56 + 16 * p + csel) * 2);
                        uint32_t b0v, b1v, b2v, b3v;
                        ldsm4t(w3_b + boff, b0v, b1v, b2v, b3v);
                        mma16816(acc3[2 * p], a0, a1, a2, a3, b0v, b1v);
                        if (p < 3) mma16816(acc3[2 * p + 1], a0, a1, a2, a3, b2v, b3v);
                    }
                }
                BAR2();
                for (int i = gt; i < 1120; i += 256) {
                    int k = i / 14, q = i - k * 14;
                    cp16(w3_b + (uint32_t)((k * W3S + 8 * q) * 2),
                         W3p + (size_t)(80 * c + k) * 112 + 8 * q);
                }
                CP_COMMIT();
            }
        }
        __syncthreads();
    }

    // ---- drain: L3 consumes chunk 4 ----
    if (!isL2) {
        CP_WAIT0();
        BAR2();
        uint32_t h2_b = sbase + OFF_H2 + 0 * H2B;     // chunk 4 -> buffer 0
        #pragma unroll
        for (int ks = 0; ks < 5; ks++) {
            uint32_t aoff = (uint32_t)(((wm * 16 + lsel) * H2S + 16 * ks + csel) * 2);
            uint32_t a0, a1, a2, a3;
            ldsm4(h2_b + aoff, a0, a1, a2, a3);
            #pragma unroll
            for (int p = 0; p < 4; p++) {
                uint32_t boff = (uint32_t)(((16 * ks + lsel) * W3S + wn * 56 + 16 * p + csel) * 2);
                uint32_t b0v, b1v, b2v, b3v;
                ldsm4t(w3_b + boff, b0v, b1v, b2v, b3v);
                mma16816(acc3[2 * p], a0, a1, a2, a3, b0v, b1v);
                if (p < 3) mma16816(acc3[2 * p + 1], a0, a1, a2, a3, b2v, b3v);
            }
        }
    }
    __syncthreads();

    // ---- h3 = relu(acc3) -> fp32 over h1/h2 region ----
    float* s_h3 = (float*)(smraw + OFF_H1);           // 64*101*4 = 25856 B
    if (!isL2) {
        #pragma unroll
        for (int nt = 0; nt < 7; nt++) {
            int n = wn * 56 + nt * 8 + 2 * tg;
            #pragma unroll
            for (int hh = 0; hh < 2; hh++) {
                int row = wm * 16 + gg + 8 * hh;
                if (n     < 100) s_h3[row * H3S + n]     = fmaxf(acc3[nt][2 * hh + 0], 0.0f);
                if (n + 1 < 100) s_h3[row * H3S + n + 1] = fmaxf(acc3[nt][2 * hh + 1], 0.0f);
            }
        }
    }
    __syncthreads();

    // ---- L4 + scatter: one thread per row, program-order stores ----
    if (t < TM) {
        int sid = s_sid[t];
        if (sid >= 0) {
            float acc[6];
            #pragma unroll
            for (int o = 0; o < 6; o++) acc[o] = __ldg(b4 + a * 6 + o);
            #pragma unroll 4
            for (int k = 0; k < 100; k++) {
                float h = s_h3[t * H3S + k];
                #pragma unroll
                for (int o = 0; o < 6; o++) acc[o] += h * s_w4[k * 6 + o];
            }
            size_t rb = (size_t)sid * XX;
            #pragma unroll
            for (int j = 0; j < 6; j++)
                out[rb + s_idx[t * 8 + j]] = s_att[t * 8 + j] + acc[j];
        }
    }
    }   // active block

    // ---- tail: last block resets counters for next graph replay ----
    if (threadIdx.x == 0) {
        int d = atomicAdd(&g_done, 1);
        if (d == NBLK - 1) {
            g_done = 0;
            g_cnt[0] = 0; g_cnt[1] = 0; g_cnt[2] = 0;
        }
    }
}

// ---------------- launch ----------------
extern "C" void kernel_launch(void* const* d_in, const int* in_sizes, int n_in,
                              void* d_out, int out_size) {
    const float* x  = (const float*)d_in[0];
    const float* W1 = (const float*)d_in[1];
    const float* b1 = (const float*)d_in[2];
    const float* W2 = (const float*)d_in[3];
    const float* b2 = (const float*)d_in[4];
    const float* W3 = (const float*)d_in[5];
    const float* b3 = (const float*)d_in[6];
    const float* W4 = (const float*)d_in[7];
    const float* b4 = (const float*)d_in[8];
    const int*   ba = (const int*)d_in[9];
    float* out = (float*)d_out;

    cudaFuncSetAttribute(k_mlp, cudaFuncAttributeMaxDynamicSharedMemorySize, SMEM_TOT);

    k_pre<<<781, 256>>>(W1, W2, W3, ba);
    dim3 g(BB / TM, 3);
    k_mlp<<<g, 512, SMEM_TOT>>>(x, b1, b2, b3, W4, b4, out);
}